// round 12
// baseline (speedup 1.0000x reference)
#include <cuda_runtime.h>
#include <stdint.h>

#define NUSERS 50000
#define NITEMS 30000
#define NNODES 80000
#define EK 64
#define HH 32
#define NNZADJ 2000000
#define NNZR 1000000
#define NCHA ((NNODES + 1023) / 1024)
#define NCHR ((NUSERS + 1023) / 1024)
#define GEMMB 235                       // (NITEMS+127)/128
#define GADJE ((NNZADJ + 255) / 256)
#define GRE   ((NNZR + 255) / 256)
#define GUSERB ((NUSERS + 7) / 8)       // 6250
#define GITMB  ((NITEMS + 7) / 8)       // 3750
#define GNODEB ((NNODES + 7) / 8)       // 10000
#define GCGEB  (GNODEB / 2)             // 5000 per y

// ---------------- scratch (device globals; allocation is forbidden) ----------------
__device__ float g_itf[2][NITEMS * EK];
__device__ float g_ihl[2][NITEMS * HH];
__device__ float g_uhl[2][NUSERS * HH];
__device__ float g_ih[2][NITEMS * HH];
__device__ float g_uh[2][NUSERS * HH];
__device__ float g_e0[NNODES * EK];          // cge (fp32)
__device__ uint32_t g_e1h[NNODES * 32];      // e1 as bf16x2 per lane-pair
__device__ float g_m0[2][NUSERS * EK];
__device__ float g_m1[2][NNODES * EK];
__device__ float g_lat[2][HH * EK];
// CSR scratch: histA, histR, flagsA, flagsR in ONE buffer (single memset)
#define HIST_TOTAL (NNODES + 1 + NUSERS + 1 + NCHA + NCHR)
__device__ int   g_hist[HIST_TOTAL];
__device__ int   g_curA[NNODES];
__device__ int   g_scolA[NNZADJ];
__device__ float g_svalA[NNZADJ];
__device__ int   g_curR[NUSERS];
__device__ int   g_scolR[NNZR];
__device__ float g_svalR[NNZR];

// ---------------- threefry2x32 (JAX-compatible, 20 rounds) ----------------
__host__ __device__ __forceinline__ void tf2x32(uint32_t k0, uint32_t k1,
                                                uint32_t x0, uint32_t x1,
                                                uint32_t* o0, uint32_t* o1) {
  uint32_t ks2 = k0 ^ k1 ^ 0x1BD11BDAu;
  uint32_t v0 = x0 + k0, v1 = x1 + k1;
#define TFR(r) { v0 += v1; v1 = (v1 << (r)) | (v1 >> (32 - (r))); v1 ^= v0; }
  TFR(13) TFR(15) TFR(26) TFR(6)
  v0 += k1;  v1 += ks2 + 1u;
  TFR(17) TFR(29) TFR(16) TFR(24)
  v0 += ks2; v1 += k0 + 2u;
  TFR(13) TFR(15) TFR(26) TFR(6)
  v0 += k0;  v1 += k1 + 3u;
  TFR(17) TFR(29) TFR(16) TFR(24)
  v0 += k1;  v1 += ks2 + 4u;
  TFR(13) TFR(15) TFR(26) TFR(6)
  v0 += ks2; v1 += k0 + 5u;
#undef TFR
  *o0 = v0; *o1 = v1;
}

// ---------------- bf16 pack/unpack + mma helpers ----------------
__device__ __forceinline__ uint2 bf16split2(float x0, float x1) {
  uint32_t h;
  asm("cvt.rn.bf16x2.f32 %0, %1, %2;" : "=r"(h) : "f"(x1), "f"(x0));
  float h0 = __uint_as_float(h << 16);
  float h1 = __uint_as_float(h & 0xFFFF0000u);
  uint32_t l;
  asm("cvt.rn.bf16x2.f32 %0, %1, %2;" : "=r"(l) : "f"(x1 - h1), "f"(x0 - h0));
  return make_uint2(h, l);
}
__device__ __forceinline__ uint32_t bf16pack(float x0, float x1) {
  uint32_t h;
  asm("cvt.rn.bf16x2.f32 %0, %1, %2;" : "=r"(h) : "f"(x1), "f"(x0));
  return h;
}
__device__ __forceinline__ float2 bf16unpack(uint32_t u) {
  return make_float2(__uint_as_float(u << 16), __uint_as_float(u & 0xFFFF0000u));
}

__device__ __forceinline__ void mma16(float* c, const uint32_t* a, const uint32_t* b) {
  asm volatile("mma.sync.aligned.m16n8k16.row.col.f32.bf16.bf16.f32 "
               "{%0,%1,%2,%3}, {%4,%5,%6,%7}, {%8,%9}, {%0,%1,%2,%3};"
               : "+f"(c[0]), "+f"(c[1]), "+f"(c[2]), "+f"(c[3])
               : "r"(a[0]), "r"(a[1]), "r"(a[2]), "r"(a[3]), "r"(b[0]), "r"(b[1]));
}

// ---------------- gumbel softmax row helper ----------------
__device__ __forceinline__ void gumbel_row(const float* __restrict__ logits,
                                           float* __restrict__ out,
                                           int row, int lane, unsigned k0, unsigned k1) {
  unsigned idx = (unsigned)row * 32u + (unsigned)lane;
  unsigned b0, b1;
  tf2x32(k0, k1, 0u, idx, &b0, &b1);
  unsigned bits = b0 ^ b1;
  float f = __uint_as_float((bits >> 9) | 0x3f800000u) - 1.0f;
  const float TINY = 1.1754943508222875e-38f;
  float u = fmaxf(TINY, f + TINY);
  float g = -logf(-logf(u));
  float z = (logits[row * 32 + lane] + g) * 5.0f;
  float mx = z;
#pragma unroll
  for (int s = 16; s; s >>= 1) mx = fmaxf(mx, __shfl_xor_sync(0xffffffffu, mx, s));
  float e = expf(z - mx);
  float sm = e;
#pragma unroll
  for (int s = 16; s; s >>= 1) sm += __shfl_xor_sync(0xffffffffu, sm, s);
  out[row * 32 + lane] = e / sm;
}

// ================= fused GEMM(bf16x3) + CSR histogram, one launch =================
#define ASP 132
#define BSP 100
__global__ __launch_bounds__(256, 2)
void gemm_hist_kernel(const float* __restrict__ A0, const float* __restrict__ A1,
                      const float* __restrict__ Bt0, const float* __restrict__ Bt1,
                      const float* __restrict__ Bh0, const float* __restrict__ Bh1,
                      float* __restrict__ Cf0, float* __restrict__ Cf1,
                      float* __restrict__ Cl0, float* __restrict__ Cl1,
                      int F0, int F1,
                      const int* __restrict__ rowsA, const int* __restrict__ rowsR,
                      int* __restrict__ cntA, int* __restrict__ cntR) {
  if (blockIdx.x >= GEMMB) {
    int hb = blockIdx.x - GEMMB;
    if (blockIdx.y == 0) {
      int e = hb * 256 + threadIdx.x;
      if (e < NNZADJ) atomicAdd(&cntA[__ldg(rowsA + e)], 1);
    } else {
      if (hb < GRE) {
        int e = hb * 256 + threadIdx.x;
        if (e < NNZR) atomicAdd(&cntR[__ldg(rowsR + e)], 1);
      }
    }
    return;
  }
  __shared__ uint2 AsP[16][ASP];
  __shared__ uint2 BsP[16][BSP];
  const int mmod = blockIdx.y;
  const float* A  = mmod ? A1 : A0;
  const float* Bt = mmod ? Bt1 : Bt0;
  const float* Bh = mmod ? Bh1 : Bh0;
  float* Cf = mmod ? Cf1 : Cf0;
  float* Cl = mmod ? Cl1 : Cl0;
  const int F = mmod ? F1 : F0;

  const int row0 = blockIdx.x * 128;
  const int tid = threadIdx.x;
  const int wid = tid >> 5, lane = tid & 31;
  const int wr = wid >> 1, wc = wid & 1;
  const int qid = lane >> 2, qtid = lane & 3;

  const int lr = tid >> 1;
  const int lk2 = (tid & 1) * 8;
  const int gr_l = row0 + lr;
  const bool rok = gr_l < NITEMS;
  const float* Arow = A + (size_t)gr_l * F + lk2 * 2;

  float4 a4[4];
  float bb0[6], bb1[6];
  const float4 z4 = make_float4(0.f, 0.f, 0.f, 0.f);
#pragma unroll
  for (int i = 0; i < 4; i++) a4[i] = rok ? __ldg((const float4*)(Arow + 4 * i)) : z4;
#pragma unroll
  for (int i = 0; i < 6; i++) {
    int p = tid + 256 * i, k2 = p / 96, c = p - k2 * 96;
    int kk = 2 * k2;
    if (c < 64) { bb0[i] = __ldg(Bt + kk * 64 + c); bb1[i] = __ldg(Bt + (kk + 1) * 64 + c); }
    else        { bb0[i] = __ldg(Bh + kk * 32 + c - 64); bb1[i] = __ldg(Bh + (kk + 1) * 32 + c - 64); }
  }

  float acc[2][6][4];
#pragma unroll
  for (int mt = 0; mt < 2; mt++)
#pragma unroll
    for (int nt = 0; nt < 6; nt++)
#pragma unroll
      for (int j = 0; j < 4; j++) acc[mt][nt][j] = 0.0f;

  for (int k0 = 0; k0 < F; k0 += 32) {
    float av[16];
#pragma unroll
    for (int i = 0; i < 4; i++) {
      av[4 * i + 0] = a4[i].x; av[4 * i + 1] = a4[i].y;
      av[4 * i + 2] = a4[i].z; av[4 * i + 3] = a4[i].w;
    }
#pragma unroll
    for (int j = 0; j < 8; j++)
      AsP[lk2 + j][lr] = bf16split2(av[2 * j], av[2 * j + 1]);
#pragma unroll
    for (int i = 0; i < 6; i++) {
      int p = tid + 256 * i, k2 = p / 96, c = p - k2 * 96;
      BsP[k2][c] = bf16split2(bb0[i], bb1[i]);
    }
    __syncthreads();
    int kn = k0 + 32;
    if (kn < F) {
#pragma unroll
      for (int i = 0; i < 4; i++) a4[i] = rok ? __ldg((const float4*)(Arow + kn + 4 * i)) : z4;
#pragma unroll
      for (int i = 0; i < 6; i++) {
        int p = tid + 256 * i, k2 = p / 96, c = p - k2 * 96;
        int kk = kn + 2 * k2;
        if (c < 64) { bb0[i] = __ldg(Bt + kk * 64 + c); bb1[i] = __ldg(Bt + (kk + 1) * 64 + c); }
        else        { bb0[i] = __ldg(Bh + kk * 32 + c - 64); bb1[i] = __ldg(Bh + (kk + 1) * 32 + c - 64); }
      }
    }
#pragma unroll
    for (int ks = 0; ks < 2; ks++) {
      const int kb = ks * 8;
      uint2 a2[2][4];
#pragma unroll
      for (int mt = 0; mt < 2; mt++) {
        int ar = wr * 32 + mt * 16 + qid;
        a2[mt][0] = AsP[kb + qtid][ar];
        a2[mt][1] = AsP[kb + qtid][ar + 8];
        a2[mt][2] = AsP[kb + qtid + 4][ar];
        a2[mt][3] = AsP[kb + qtid + 4][ar + 8];
      }
#pragma unroll
      for (int nt = 0; nt < 6; nt++) {
        int bn = wc * 48 + nt * 8 + qid;
        uint2 b0 = BsP[kb + qtid][bn];
        uint2 b1 = BsP[kb + qtid + 4][bn];
        uint32_t bhv[2] = {b0.x, b1.x};
        uint32_t blv[2] = {b0.y, b1.y};
#pragma unroll
        for (int mt = 0; mt < 2; mt++) {
          uint32_t ah[4] = {a2[mt][0].x, a2[mt][1].x, a2[mt][2].x, a2[mt][3].x};
          uint32_t al[4] = {a2[mt][0].y, a2[mt][1].y, a2[mt][2].y, a2[mt][3].y};
          mma16(acc[mt][nt], ah, bhv);
          mma16(acc[mt][nt], ah, blv);
          mma16(acc[mt][nt], al, bhv);
        }
      }
    }
    __syncthreads();
  }

#pragma unroll
  for (int mt = 0; mt < 2; mt++) {
    int gr = row0 + wr * 32 + mt * 16 + qid;
#pragma unroll
    for (int nt = 0; nt < 6; nt++) {
      int cc = wc * 48 + nt * 8 + 2 * qtid;
      if (gr < NITEMS) {
        if (cc < 64) { Cf[gr * 64 + cc] = acc[mt][nt][0]; Cf[gr * 64 + cc + 1] = acc[mt][nt][1]; }
        else         { Cl[gr * 32 + cc - 64] = acc[mt][nt][0]; Cl[gr * 32 + cc - 63] = acc[mt][nt][1]; }
      }
      if (gr + 8 < NITEMS) {
        if (cc < 64) { Cf[(gr + 8) * 64 + cc] = acc[mt][nt][2]; Cf[(gr + 8) * 64 + cc + 1] = acc[mt][nt][3]; }
        else         { Cl[(gr + 8) * 32 + cc - 64] = acc[mt][nt][2]; Cl[(gr + 8) * 32 + cc - 63] = acc[mt][nt][3]; }
      }
    }
  }
}

// ================= single-pass chained scan (replaces 3 scan launches) =================
// blockIdx.x < NCHA: segment A chunk; else segment R chunk. Chain via flags (value = prefix+total+1).
__global__ void csr_scan_chain(int* __restrict__ cntA, int* __restrict__ curA, int* __restrict__ flagA,
                               int* __restrict__ cntB, int* __restrict__ curB, int* __restrict__ flagB) {
  __shared__ int sm[1024];
  __shared__ int ts[256];
  __shared__ int sh_prefix;
  int* cnt;
  int* cur;
  int* flag;
  int n, nnz, ch, nch;
  if (blockIdx.x < NCHA) { cnt = cntA; cur = curA; flag = flagA; n = NNODES; nnz = NNZADJ; ch = blockIdx.x; nch = NCHA; }
  else                   { cnt = cntB; cur = curB; flag = flagB; n = NUSERS; nnz = NNZR; ch = blockIdx.x - NCHA; nch = NCHR; }
  int base = ch * 1024;
  for (int i = threadIdx.x; i < 1024; i += 256)
    sm[i] = (base + i < n) ? cnt[base + i] : 0;
  __syncthreads();
  int t = threadIdx.x;
  int a0 = sm[t * 4], a1 = sm[t * 4 + 1], a2 = sm[t * 4 + 2], a3 = sm[t * 4 + 3];
  int local = a0 + a1 + a2 + a3;
  ts[t] = local;
  __syncthreads();
  for (int off = 1; off < 256; off <<= 1) {
    int v = (t >= off) ? ts[t - off] : 0;
    __syncthreads();
    ts[t] += v;
    __syncthreads();
  }
  int total = ts[255];
  if (t == 0) {
    int prefix = 0;
    if (ch > 0) {
      volatile int* f = flag + ch - 1;
      int v;
      while ((v = *f) == 0) { }
      prefix = v - 1;
    }
    sh_prefix = prefix;
    __threadfence();
    flag[ch] = prefix + total + 1;   // unblock successor ASAP
  }
  __syncthreads();
  int prefix = sh_prefix;
  int excl = ts[t] - local + prefix;
  int i0 = base + t * 4;
  if (i0 + 0 < n) { cnt[i0 + 0] = excl;                cur[i0 + 0] = excl; }
  if (i0 + 1 < n) { cnt[i0 + 1] = excl + a0;           cur[i0 + 1] = excl + a0; }
  if (i0 + 2 < n) { cnt[i0 + 2] = excl + a0 + a1;      cur[i0 + 2] = excl + a0 + a1; }
  if (i0 + 3 < n) { cnt[i0 + 3] = excl + a0 + a1 + a2; cur[i0 + 3] = excl + a0 + a1 + a2; }
  if (ch == nch - 1 && t == 0) cnt[n] = nnz;
}

__global__ void csr_scatter2(const int* __restrict__ rowsA, const int* __restrict__ colsA,
                             const float* __restrict__ valsA, int* __restrict__ curA,
                             int* __restrict__ scolA, float* __restrict__ svalA,
                             const int* __restrict__ rowsB, const int* __restrict__ colsB,
                             const float* __restrict__ valsB, int* __restrict__ curB,
                             int* __restrict__ scolB, float* __restrict__ svalB) {
  int b = blockIdx.x;
  if (b < GADJE) {
    int e = b * 256 + threadIdx.x;
    if (e >= NNZADJ) return;
    int r = __ldg(rowsA + e);
    int p = atomicAdd(&curA[r], 1);
    scolA[p] = __ldg(colsA + e);
    svalA[p] = __ldg(valsA + e);
  } else {
    int e = (b - GADJE) * 256 + threadIdx.x;
    if (e >= NNZR) return;
    int r = __ldg(rowsB + e);
    int p = atomicAdd(&curB[r], 1);
    scolB[p] = __ldg(colsB + e);
    svalB[p] = __ldg(valsB + e);
  }
}

// ================= phase 2: r_fused + gumbel-items + cge1(bf16 out) =================
__global__ void phase2_kernel(const int* __restrict__ startR, const int* __restrict__ scolR,
                              const float* __restrict__ svalR,
                              const float* __restrict__ ihl0, const float* __restrict__ ihl1,
                              const float2* __restrict__ itf0, const float2* __restrict__ itf1,
                              float* __restrict__ uhl0, float* __restrict__ uhl1,
                              float2* __restrict__ m00, float2* __restrict__ m01,
                              float* __restrict__ ih0, float* __restrict__ ih1,
                              unsigned ki00, unsigned ki01, unsigned ki10, unsigned ki11,
                              const int* __restrict__ startA, const int* __restrict__ scolA,
                              const float* __restrict__ svalA,
                              const float2* __restrict__ Gu, const float2* __restrict__ Gi,
                              uint32_t* __restrict__ e1h) {
  int bx = blockIdx.x;
  int wid = threadIdx.x >> 5, lane = threadIdx.x & 31;
  if (bx < GUSERB) {
    int row = bx * 8 + wid;
    if (row >= NUSERS) return;
    const float* xs = blockIdx.y ? ihl1 : ihl0;
    const float2* xd = blockIdx.y ? itf1 : itf0;
    float* ys = blockIdx.y ? uhl1 : uhl0;
    float2* yd = blockIdx.y ? m01 : m00;
    int s = startR[row], e = startR[row + 1];
    float a = 0.f, ax = 0.f, ay = 0.f;
    int i = s;
    for (; i + 1 < e; i += 2) {
      int c0 = __ldg(scolR + i), c1 = __ldg(scolR + i + 1);
      float v0 = __ldg(svalR + i), v1 = __ldg(svalR + i + 1);
      float s0 = __ldg(xs + (size_t)c0 * 32 + lane);
      float s1 = __ldg(xs + (size_t)c1 * 32 + lane);
      float2 d0 = __ldg(xd + (size_t)c0 * 32 + lane);
      float2 d1 = __ldg(xd + (size_t)c1 * 32 + lane);
      a = fmaf(v0, s0, a); ax = fmaf(v0, d0.x, ax); ay = fmaf(v0, d0.y, ay);
      a = fmaf(v1, s1, a); ax = fmaf(v1, d1.x, ax); ay = fmaf(v1, d1.y, ay);
    }
    for (; i < e; i++) {
      int c = __ldg(scolR + i);
      float v = __ldg(svalR + i);
      a = fmaf(v, __ldg(xs + (size_t)c * 32 + lane), a);
      float2 d = __ldg(xd + (size_t)c * 32 + lane);
      ax = fmaf(v, d.x, ax); ay = fmaf(v, d.y, ay);
    }
    ys[(size_t)row * 32 + lane] = a;
    yd[(size_t)row * 32 + lane] = make_float2(ax, ay);
  } else if (bx < GUSERB + GITMB) {
    int row = (bx - GUSERB) * 8 + wid;
    if (row >= NITEMS) return;
    const float* lg = blockIdx.y ? ihl1 : ihl0;
    float* o = blockIdx.y ? ih1 : ih0;
    unsigned k0 = blockIdx.y ? ki10 : ki00;
    unsigned k1 = blockIdx.y ? ki11 : ki01;
    gumbel_row(lg, o, row, lane, k0, k1);
  } else {
    int row = ((bx - GUSERB - GITMB) + blockIdx.y * GCGEB) * 8 + wid;
    if (row >= NNODES) return;
    int s = startA[row], e = startA[row + 1];
    float ax = 0.f, ay = 0.f;
    int i = s;
    for (; i + 1 < e; i += 2) {
      int c0 = __ldg(scolA + i), c1 = __ldg(scolA + i + 1);
      float v0 = __ldg(svalA + i), v1 = __ldg(svalA + i + 1);
      const float2* x0p = (c0 < NUSERS) ? Gu + (size_t)c0 * 32 : Gi + (size_t)(c0 - NUSERS) * 32;
      const float2* x1p = (c1 < NUSERS) ? Gu + (size_t)c1 * 32 : Gi + (size_t)(c1 - NUSERS) * 32;
      float2 x0 = __ldg(x0p + lane), x1 = __ldg(x1p + lane);
      ax = fmaf(v0, x0.x, ax); ay = fmaf(v0, x0.y, ay);
      ax = fmaf(v1, x1.x, ax); ay = fmaf(v1, x1.y, ay);
    }
    for (; i < e; i++) {
      int c = __ldg(scolA + i);
      float v = __ldg(svalA + i);
      const float2* xp = (c < NUSERS) ? Gu + (size_t)c * 32 : Gi + (size_t)(c - NUSERS) * 32;
      float2 xv = __ldg(xp + lane);
      ax = fmaf(v, xv.x, ax); ay = fmaf(v, xv.y, ay);
    }
    e1h[(size_t)row * 32 + lane] = bf16pack(ax, ay);
  }
}

// ================= phase 3: mega adj pass (cge2+combine, mge both) + gumbel-u =================
__global__ void phase3_kernel(const int* __restrict__ startA, const int* __restrict__ scolA,
                              const float* __restrict__ svalA,
                              const uint32_t* __restrict__ e1h,
                              const float2* __restrict__ Gu, const float2* __restrict__ Gi,
                              float2* __restrict__ cge,
                              const float2* __restrict__ m00, const float2* __restrict__ m01,
                              const float2* __restrict__ itf0, const float2* __restrict__ itf1,
                              const float* __restrict__ inv,
                              float2* __restrict__ m10, float2* __restrict__ m11,
                              const float* __restrict__ uhl0, const float* __restrict__ uhl1,
                              float* __restrict__ uh0, float* __restrict__ uh1,
                              unsigned ku00, unsigned ku01, unsigned ku10, unsigned ku11) {
  int bx = blockIdx.x;
  int wid = threadIdx.x >> 5, lane = threadIdx.x & 31;
  if (bx < GNODEB) {
    int row = bx * 8 + wid;
    if (row >= NNODES) return;
    int s = startA[row], e = startA[row + 1];
    float ex = 0.f, ey = 0.f;
    float vx = 0.f, vy = 0.f;
    float tx = 0.f, ty = 0.f;
    int i = s;
    for (; i + 1 < e; i += 2) {
      int c0 = __ldg(scolA + i), c1 = __ldg(scolA + i + 1);
      float v0 = __ldg(svalA + i), v1 = __ldg(svalA + i + 1);
      uint32_t u0 = __ldg(e1h + (size_t)c0 * 32 + lane);
      uint32_t u1 = __ldg(e1h + (size_t)c1 * 32 + lane);
      float vm0 = v0, vm1 = v1;
      const float2 *sv0, *st0, *sv1, *st1;
      if (c0 < NUSERS) { vm0 = v0 * __ldg(inv + c0); sv0 = m00 + (size_t)c0 * 32; st0 = m01 + (size_t)c0 * 32; }
      else             { sv0 = itf0 + (size_t)(c0 - NUSERS) * 32; st0 = itf1 + (size_t)(c0 - NUSERS) * 32; }
      if (c1 < NUSERS) { vm1 = v1 * __ldg(inv + c1); sv1 = m00 + (size_t)c1 * 32; st1 = m01 + (size_t)c1 * 32; }
      else             { sv1 = itf0 + (size_t)(c1 - NUSERS) * 32; st1 = itf1 + (size_t)(c1 - NUSERS) * 32; }
      float2 dv0 = __ldg(sv0 + lane), dt0 = __ldg(st0 + lane);
      float2 dv1 = __ldg(sv1 + lane), dt1 = __ldg(st1 + lane);
      float2 ev0 = bf16unpack(u0), ev1 = bf16unpack(u1);
      ex = fmaf(v0, ev0.x, ex); ey = fmaf(v0, ev0.y, ey);
      vx = fmaf(vm0, dv0.x, vx); vy = fmaf(vm0, dv0.y, vy);
      tx = fmaf(vm0, dt0.x, tx); ty = fmaf(vm0, dt0.y, ty);
      ex = fmaf(v1, ev1.x, ex); ey = fmaf(v1, ev1.y, ey);
      vx = fmaf(vm1, dv1.x, vx); vy = fmaf(vm1, dv1.y, vy);
      tx = fmaf(vm1, dt1.x, tx); ty = fmaf(vm1, dt1.y, ty);
    }
    for (; i < e; i++) {
      int c = __ldg(scolA + i);
      float v = __ldg(svalA + i);
      float2 ev = bf16unpack(__ldg(e1h + (size_t)c * 32 + lane));
      float vm = v;
      const float2 *sv, *st;
      if (c < NUSERS) { vm = v * __ldg(inv + c); sv = m00 + (size_t)c * 32; st = m01 + (size_t)c * 32; }
      else            { sv = itf0 + (size_t)(c - NUSERS) * 32; st = itf1 + (size_t)(c - NUSERS) * 32; }
      float2 dv = __ldg(sv + lane), dt = __ldg(st + lane);
      ex = fmaf(v, ev.x, ex); ey = fmaf(v, ev.y, ey);
      vx = fmaf(vm, dv.x, vx); vy = fmaf(vm, dv.y, vy);
      tx = fmaf(vm, dt.x, tx); ty = fmaf(vm, dt.y, ty);
    }
    float2 ego = (row < NUSERS) ? __ldg(Gu + (size_t)row * 32 + lane)
                                : __ldg(Gi + (size_t)(row - NUSERS) * 32 + lane);
    float2 e1v = bf16unpack(e1h[(size_t)row * 32 + lane]);
    cge[(size_t)row * 32 + lane] = make_float2((ego.x + e1v.x + ex) * (1.0f / 3.0f),
                                               (ego.y + e1v.y + ey) * (1.0f / 3.0f));
    m10[(size_t)row * 32 + lane] = make_float2(vx, vy);
    m11[(size_t)row * 32 + lane] = make_float2(tx, ty);
  } else if (bx < GNODEB + GUSERB) {
    int row = (bx - GNODEB) * 8 + wid;
    if (row >= NUSERS) return;
    gumbel_row(uhl0, uh0, row, lane, ku00, ku01);
  } else {
    int row = (bx - GNODEB - GUSERB) * 8 + wid;
    if (row >= NUSERS) return;
    gumbel_row(uhl1, uh1, row, lane, ku10, ku11);
  }
}

// ---------------- lat[32,64] += ih^T @ icge, both modalities (lat pre-zeroed) ----------------
__global__ void lat_both_kernel(const float* __restrict__ w0, const float* __restrict__ w1,
                                const float* __restrict__ icge,
                                float* __restrict__ lat0, float* __restrict__ lat1, int chunk) {
  const float* w = blockIdx.y ? w1 : w0;
  float* lat = blockIdx.y ? lat1 : lat0;
  int lane = threadIdx.x & 31;
  int kg = threadIdx.x >> 5;
  int start = blockIdx.x * chunk;
  int end = min(start + chunk, NITEMS);
  float acc[8] = {0, 0, 0, 0, 0, 0, 0, 0};
  for (int it = start; it < end; ++it) {
    float wv = w[it * HH + lane];
    const float* cr = icge + it * EK + kg * 8;
#pragma unroll
    for (int j = 0; j < 8; j++) acc[j] = fmaf(wv, __ldg(cr + j), acc[j]);
  }
#pragma unroll
  for (int j = 0; j < 8; j++) atomicAdd(&lat[lane * EK + kg * 8 + j], acc[j]);
}

// ---------------- fused hyper-apply + final, warp per row ----------------
#define OI   (NUSERS * EK)
#define OHVU ((NUSERS + NITEMS) * EK)
#define OHVI (OHVU + NUSERS * EK)
#define OHTU (OHVI + NITEMS * EK)
#define OHTI (OHTU + NUSERS * EK)
__global__ void final_fused(float* __restrict__ out, const float* __restrict__ cge,
                            const float* __restrict__ m1a, const float* __restrict__ m1b,
                            const float* __restrict__ ih0, const float* __restrict__ ih1,
                            const float* __restrict__ uh0, const float* __restrict__ uh1,
                            const float* __restrict__ lat0, const float* __restrict__ lat1) {
  __shared__ float slA[HH * EK];
  __shared__ float slB[HH * EK];
  for (int t = threadIdx.x; t < HH * EK; t += 256) { slA[t] = lat0[t]; slB[t] = lat1[t]; }
  __syncthreads();
  int row = blockIdx.x * 8 + (threadIdx.x >> 5);
  if (row >= NNODES) return;
  int lane = threadIdx.x & 31;
  const float* w0;
  const float* w1;
  float *outV, *outT, *dst;
  if (row < NUSERS) {
    w0 = uh0 + row * HH; w1 = uh1 + row * HH;
    outV = out + OHVU + row * EK; outT = out + OHTU + row * EK;
    dst = out + row * EK;
  } else {
    int ir = row - NUSERS;
    w0 = ih0 + ir * HH; w1 = ih1 + ir * HH;
    outV = out + OHVI + ir * EK; outT = out + OHTI + ir * EK;
    dst = out + OI + ir * EK;
  }
  float wl0 = w0[lane], wl1 = w1[lane];
  float s0 = 0.f, s1 = 0.f, t0 = 0.f, t1 = 0.f;
#pragma unroll
  for (int h = 0; h < HH; h++) {
    float wv0 = __shfl_sync(0xffffffffu, wl0, h);
    float wv1 = __shfl_sync(0xffffffffu, wl1, h);
    s0 = fmaf(wv0, slA[h * EK + lane], s0);
    s1 = fmaf(wv0, slA[h * EK + lane + 32], s1);
    t0 = fmaf(wv1, slB[h * EK + lane], t0);
    t1 = fmaf(wv1, slB[h * EK + lane + 32], t1);
  }
  outV[lane] = s0; outV[lane + 32] = s1;
  outT[lane] = t0; outT[lane + 32] = t1;
  int b = row * EK;
  float a0 = m1a[b + lane], a1 = m1a[b + lane + 32];
  float c0 = m1b[b + lane], c1 = m1b[b + lane + 32];
  float g0 = s0 + t0, g1 = s1 + t1;
  float sa = a0 * a0 + a1 * a1;
  float sc = c0 * c0 + c1 * c1;
  float sg = g0 * g0 + g1 * g1;
#pragma unroll
  for (int s = 16; s; s >>= 1) {
    sa += __shfl_xor_sync(0xffffffffu, sa, s);
    sc += __shfl_xor_sync(0xffffffffu, sc, s);
    sg += __shfl_xor_sync(0xffffffffu, sg, s);
  }
  float ia = 1.0f / fmaxf(sqrtf(sa), 1e-12f);
  float ic = 1.0f / fmaxf(sqrtf(sc), 1e-12f);
  float ig = 0.2f / fmaxf(sqrtf(sg), 1e-12f);
  dst[lane]      = cge[b + lane]      + a0 * ia + c0 * ic + g0 * ig;
  dst[lane + 32] = cge[b + lane + 32] + a1 * ia + c1 * ic + g1 * ig;
}

// ================================================================================
extern "C" void kernel_launch(void* const* d_in, const int* in_sizes, int n_in,
                              void* d_out, int out_size) {
  const float* Gu       = (const float*)d_in[0];
  const float* Gi       = (const float*)d_in[1];
  const float* feat_v   = (const float*)d_in[2];
  const float* feat_t   = (const float*)d_in[3];
  const float* trs_v    = (const float*)d_in[4];
  const float* trs_t    = (const float*)d_in[5];
  const float* hyp_v    = (const float*)d_in[6];
  const float* hyp_t    = (const float*)d_in[7];
  const float* inv      = (const float*)d_in[8];
  const float* adj_vals = (const float*)d_in[9];
  const float* r_vals   = (const float*)d_in[10];
  const int*   adj_rows = (const int*)d_in[11];
  const int*   adj_cols = (const int*)d_in[12];
  const int*   r_rows   = (const int*)d_in[13];
  const int*   r_cols   = (const int*)d_in[14];
  float* out = (float*)d_out;
  int Fv = in_sizes[2] / NITEMS;
  int Ft = in_sizes[3] / NITEMS;

  float *p_itf, *p_ihl, *p_uhl, *p_ih, *p_uh, *p_e0, *p_m0, *p_m1, *p_lat;
  uint32_t* p_e1h;
  int *p_hist, *pA_cur, *pA_scol, *pR_cur, *pR_scol;
  float *pA_sval, *pR_sval;
  cudaGetSymbolAddress((void**)&p_itf, g_itf);
  cudaGetSymbolAddress((void**)&p_ihl, g_ihl);
  cudaGetSymbolAddress((void**)&p_uhl, g_uhl);
  cudaGetSymbolAddress((void**)&p_ih,  g_ih);
  cudaGetSymbolAddress((void**)&p_uh,  g_uh);
  cudaGetSymbolAddress((void**)&p_e0,  g_e0);
  cudaGetSymbolAddress((void**)&p_e1h, g_e1h);
  cudaGetSymbolAddress((void**)&p_m0,  g_m0);
  cudaGetSymbolAddress((void**)&p_m1,  g_m1);
  cudaGetSymbolAddress((void**)&p_lat, g_lat);
  cudaGetSymbolAddress((void**)&p_hist, g_hist);
  cudaGetSymbolAddress((void**)&pA_cur,  g_curA);
  cudaGetSymbolAddress((void**)&pA_scol, g_scolA);
  cudaGetSymbolAddress((void**)&pA_sval, g_svalA);
  cudaGetSymbolAddress((void**)&pR_cur,  g_curR);
  cudaGetSymbolAddress((void**)&pR_scol, g_scolR);
  cudaGetSymbolAddress((void**)&pR_sval, g_svalR);
  int* pA_start = p_hist;
  int* pR_start = p_hist + NNODES + 1;
  int* pA_flag  = pR_start + NUSERS + 1;
  int* pR_flag  = pA_flag + NCHA;
  float* p_itfT = p_itf + NITEMS * EK;
  float* p_ihlT = p_ihl + NITEMS * HH;
  float* p_uhlT = p_uhl + NUSERS * HH;
  float* p_ihT  = p_ih + NITEMS * HH;
  float* p_uhT  = p_uh + NUSERS * HH;
  float* p_m0T  = p_m0 + NUSERS * EK;
  float* p_m1T  = p_m1 + NNODES * EK;
  float* p_latT = p_lat + HH * EK;

  // JAX threefry keys
  uint32_t ki0[2], ki1[2], ku0[2], ku1[2];
  for (int m = 0; m < 2; m++) {
    uint32_t km0, km1;
    tf2x32(0u, 42u, 0u, (uint32_t)m, &km0, &km1);
    tf2x32(km0, km1, 0u, 0u, &ki0[m], &ki1[m]);
    tf2x32(km0, km1, 0u, 1u, &ku0[m], &ku1[m]);
  }

  // ---- zero CSR histograms + chain flags (one memset) + lat ----
  cudaMemsetAsync(p_hist, 0, HIST_TOTAL * sizeof(int), 0);
  cudaMemsetAsync(p_lat, 0, 2 * HH * EK * sizeof(float), 0);

  // ---- GEMMs + CSR histograms in one launch ----
  gemm_hist_kernel<<<dim3(GEMMB + GADJE, 2), 256>>>(
      feat_v, feat_t, trs_v, trs_t, hyp_v, hyp_t,
      p_itf, p_itfT, p_ihl, p_ihlT, Fv, Ft,
      adj_rows, r_rows, pA_start, pR_start);

  // ---- single-pass chained scan + scatter ----
  csr_scan_chain<<<NCHA + NCHR, 256>>>(pA_start, pA_cur, pA_flag,
                                       pR_start, pR_cur, pR_flag);
  csr_scatter2<<<GADJE + GRE, 256>>>(adj_rows, adj_cols, adj_vals, pA_cur, pA_scol, pA_sval,
                                     r_rows, r_cols, r_vals, pR_cur, pR_scol, pR_sval);

  // ---- phase 2: r_fused + gumbel-items + cge1 ----
  phase2_kernel<<<dim3(GUSERB + GITMB + GCGEB, 2), 256>>>(
      pR_start, pR_scol, pR_sval,
      p_ihl, p_ihlT, (const float2*)p_itf, (const float2*)p_itfT,
      p_uhl, p_uhlT, (float2*)p_m0, (float2*)p_m0T,
      p_ih, p_ihT, ki0[0], ki1[0], ki0[1], ki1[1],
      pA_start, pA_scol, pA_sval,
      (const float2*)Gu, (const float2*)Gi, p_e1h);

  // ---- phase 3: mega adj (cge2 + mge both) + gumbel-u ----
  phase3_kernel<<<GNODEB + 2 * GUSERB, 256>>>(
      pA_start, pA_scol, pA_sval, p_e1h,
      (const float2*)Gu, (const float2*)Gi, (float2*)p_e0,
      (const float2*)p_m0, (const float2*)p_m0T,
      (const float2*)p_itf, (const float2*)p_itfT, inv,
      (float2*)p_m1, (float2*)p_m1T,
      p_uhl, p_uhlT, p_uh, p_uhT, ku0[0], ku1[0], ku0[1], ku1[1]);

  // ---- hyper path + final ----
  lat_both_kernel<<<dim3(120, 2), 256>>>(p_ih, p_ihT, p_e0 + NUSERS * EK, p_lat, p_latT, 250);
  final_fused<<<GNODEB, 256>>>(out, p_e0, p_m1, p_m1T,
                               p_ih, p_ihT, p_uh, p_uhT, p_lat, p_latT);
}

// round 13
// speedup vs baseline: 1.0443x; 1.0443x over previous
#include <cuda_runtime.h>
#include <stdint.h>

#define NUSERS 50000
#define NITEMS 30000
#define NNODES 80000
#define EK 64
#define HH 32
#define NNZADJ 2000000
#define NNZR 1000000
#define NCHA ((NNODES + 1023) / 1024)
#define NCHR ((NUSERS + 1023) / 1024)
#define GEMMB 235                       // (NITEMS+127)/128
#define GADJE ((NNZADJ + 255) / 256)
#define GRE   ((NNZR + 255) / 256)
#define GUSERB ((NUSERS + 7) / 8)       // 6250
#define GITMB  ((NITEMS + 7) / 8)       // 3750
#define GNODEB ((NNODES + 7) / 8)       // 10000
#define GCGEB  (GNODEB / 2)             // 5000 per y

// ---------------- scratch (device globals; allocation is forbidden) ----------------
__device__ float g_itf[2][NITEMS * EK];
__device__ float g_ihl[2][NITEMS * HH];
__device__ float g_uhl[2][NUSERS * HH];
__device__ float g_ih[2][NITEMS * HH];
__device__ float g_uh[2][NUSERS * HH];
__device__ float g_e0[NNODES * EK];          // cge (fp32)
__device__ uint32_t g_e1h[NNODES * 32];      // e1 as bf16x2 per lane-pair
__device__ float g_m0[2][NUSERS * EK];
__device__ float g_m1[2][NNODES * EK];
__device__ float g_lat[2][HH * EK];
// CSR scratch: histA and histR in ONE buffer (single memset)
#define HIST_TOTAL (NNODES + 1 + NUSERS + 1)
__device__ int   g_hist[HIST_TOTAL];
__device__ int   g_curA[NNODES];
__device__ int   g_scolA[NNZADJ];
__device__ float g_svalA[NNZADJ];
__device__ int   g_csumA[NCHA];
__device__ int   g_coffA[NCHA];
__device__ int   g_curR[NUSERS];
__device__ int   g_scolR[NNZR];
__device__ float g_svalR[NNZR];
__device__ int   g_csumR[NCHR];
__device__ int   g_coffR[NCHR];

// ---------------- threefry2x32 (JAX-compatible, 20 rounds) ----------------
__host__ __device__ __forceinline__ void tf2x32(uint32_t k0, uint32_t k1,
                                                uint32_t x0, uint32_t x1,
                                                uint32_t* o0, uint32_t* o1) {
  uint32_t ks2 = k0 ^ k1 ^ 0x1BD11BDAu;
  uint32_t v0 = x0 + k0, v1 = x1 + k1;
#define TFR(r) { v0 += v1; v1 = (v1 << (r)) | (v1 >> (32 - (r))); v1 ^= v0; }
  TFR(13) TFR(15) TFR(26) TFR(6)
  v0 += k1;  v1 += ks2 + 1u;
  TFR(17) TFR(29) TFR(16) TFR(24)
  v0 += ks2; v1 += k0 + 2u;
  TFR(13) TFR(15) TFR(26) TFR(6)
  v0 += k0;  v1 += k1 + 3u;
  TFR(17) TFR(29) TFR(16) TFR(24)
  v0 += k1;  v1 += ks2 + 4u;
  TFR(13) TFR(15) TFR(26) TFR(6)
  v0 += ks2; v1 += k0 + 5u;
#undef TFR
  *o0 = v0; *o1 = v1;
}

// ---------------- bf16 pack/unpack + mma helpers ----------------
__device__ __forceinline__ uint2 bf16split2(float x0, float x1) {
  uint32_t h;
  asm("cvt.rn.bf16x2.f32 %0, %1, %2;" : "=r"(h) : "f"(x1), "f"(x0));
  float h0 = __uint_as_float(h << 16);
  float h1 = __uint_as_float(h & 0xFFFF0000u);
  uint32_t l;
  asm("cvt.rn.bf16x2.f32 %0, %1, %2;" : "=r"(l) : "f"(x1 - h1), "f"(x0 - h0));
  return make_uint2(h, l);
}
__device__ __forceinline__ uint32_t bf16pack(float x0, float x1) {
  uint32_t h;
  asm("cvt.rn.bf16x2.f32 %0, %1, %2;" : "=r"(h) : "f"(x1), "f"(x0));
  return h;
}
__device__ __forceinline__ float2 bf16unpack(uint32_t u) {
  return make_float2(__uint_as_float(u << 16), __uint_as_float(u & 0xFFFF0000u));
}

__device__ __forceinline__ void mma16(float* c, const uint32_t* a, const uint32_t* b) {
  asm volatile("mma.sync.aligned.m16n8k16.row.col.f32.bf16.bf16.f32 "
               "{%0,%1,%2,%3}, {%4,%5,%6,%7}, {%8,%9}, {%0,%1,%2,%3};"
               : "+f"(c[0]), "+f"(c[1]), "+f"(c[2]), "+f"(c[3])
               : "r"(a[0]), "r"(a[1]), "r"(a[2]), "r"(a[3]), "r"(b[0]), "r"(b[1]));
}

// ---------------- gumbel softmax row helper ----------------
__device__ __forceinline__ void gumbel_row(const float* __restrict__ logits,
                                           float* __restrict__ out,
                                           int row, int lane, unsigned k0, unsigned k1) {
  unsigned idx = (unsigned)row * 32u + (unsigned)lane;
  unsigned b0, b1;
  tf2x32(k0, k1, 0u, idx, &b0, &b1);
  unsigned bits = b0 ^ b1;
  float f = __uint_as_float((bits >> 9) | 0x3f800000u) - 1.0f;
  const float TINY = 1.1754943508222875e-38f;
  float u = fmaxf(TINY, f + TINY);
  float g = -logf(-logf(u));
  float z = (logits[row * 32 + lane] + g) * 5.0f;
  float mx = z;
#pragma unroll
  for (int s = 16; s; s >>= 1) mx = fmaxf(mx, __shfl_xor_sync(0xffffffffu, mx, s));
  float e = expf(z - mx);
  float sm = e;
#pragma unroll
  for (int s = 16; s; s >>= 1) sm += __shfl_xor_sync(0xffffffffu, sm, s);
  out[row * 32 + lane] = e / sm;
}

// ================= fused GEMM(bf16x3) + CSR histogram, one launch =================
#define ASP 132
#define BSP 100
__global__ __launch_bounds__(256, 2)
void gemm_hist_kernel(const float* __restrict__ A0, const float* __restrict__ A1,
                      const float* __restrict__ Bt0, const float* __restrict__ Bt1,
                      const float* __restrict__ Bh0, const float* __restrict__ Bh1,
                      float* __restrict__ Cf0, float* __restrict__ Cf1,
                      float* __restrict__ Cl0, float* __restrict__ Cl1,
                      int F0, int F1,
                      const int* __restrict__ rowsA, const int* __restrict__ rowsR,
                      int* __restrict__ cntA, int* __restrict__ cntR) {
  if (blockIdx.x >= GEMMB) {
    int hb = blockIdx.x - GEMMB;
    if (blockIdx.y == 0) {
      int e = hb * 256 + threadIdx.x;
      if (e < NNZADJ) atomicAdd(&cntA[__ldg(rowsA + e)], 1);
    } else {
      if (hb < GRE) {
        int e = hb * 256 + threadIdx.x;
        if (e < NNZR) atomicAdd(&cntR[__ldg(rowsR + e)], 1);
      }
    }
    return;
  }
  __shared__ uint2 AsP[16][ASP];
  __shared__ uint2 BsP[16][BSP];
  const int mmod = blockIdx.y;
  const float* A  = mmod ? A1 : A0;
  const float* Bt = mmod ? Bt1 : Bt0;
  const float* Bh = mmod ? Bh1 : Bh0;
  float* Cf = mmod ? Cf1 : Cf0;
  float* Cl = mmod ? Cl1 : Cl0;
  const int F = mmod ? F1 : F0;

  const int row0 = blockIdx.x * 128;
  const int tid = threadIdx.x;
  const int wid = tid >> 5, lane = tid & 31;
  const int wr = wid >> 1, wc = wid & 1;
  const int qid = lane >> 2, qtid = lane & 3;

  const int lr = tid >> 1;
  const int lk2 = (tid & 1) * 8;
  const int gr_l = row0 + lr;
  const bool rok = gr_l < NITEMS;
  const float* Arow = A + (size_t)gr_l * F + lk2 * 2;

  float4 a4[4];
  float bb0[6], bb1[6];
  const float4 z4 = make_float4(0.f, 0.f, 0.f, 0.f);
#pragma unroll
  for (int i = 0; i < 4; i++) a4[i] = rok ? __ldg((const float4*)(Arow + 4 * i)) : z4;
#pragma unroll
  for (int i = 0; i < 6; i++) {
    int p = tid + 256 * i, k2 = p / 96, c = p - k2 * 96;
    int kk = 2 * k2;
    if (c < 64) { bb0[i] = __ldg(Bt + kk * 64 + c); bb1[i] = __ldg(Bt + (kk + 1) * 64 + c); }
    else        { bb0[i] = __ldg(Bh + kk * 32 + c - 64); bb1[i] = __ldg(Bh + (kk + 1) * 32 + c - 64); }
  }

  float acc[2][6][4];
#pragma unroll
  for (int mt = 0; mt < 2; mt++)
#pragma unroll
    for (int nt = 0; nt < 6; nt++)
#pragma unroll
      for (int j = 0; j < 4; j++) acc[mt][nt][j] = 0.0f;

  for (int k0 = 0; k0 < F; k0 += 32) {
    float av[16];
#pragma unroll
    for (int i = 0; i < 4; i++) {
      av[4 * i + 0] = a4[i].x; av[4 * i + 1] = a4[i].y;
      av[4 * i + 2] = a4[i].z; av[4 * i + 3] = a4[i].w;
    }
#pragma unroll
    for (int j = 0; j < 8; j++)
      AsP[lk2 + j][lr] = bf16split2(av[2 * j], av[2 * j + 1]);
#pragma unroll
    for (int i = 0; i < 6; i++) {
      int p = tid + 256 * i, k2 = p / 96, c = p - k2 * 96;
      BsP[k2][c] = bf16split2(bb0[i], bb1[i]);
    }
    __syncthreads();
    int kn = k0 + 32;
    if (kn < F) {
#pragma unroll
      for (int i = 0; i < 4; i++) a4[i] = rok ? __ldg((const float4*)(Arow + kn + 4 * i)) : z4;
#pragma unroll
      for (int i = 0; i < 6; i++) {
        int p = tid + 256 * i, k2 = p / 96, c = p - k2 * 96;
        int kk = kn + 2 * k2;
        if (c < 64) { bb0[i] = __ldg(Bt + kk * 64 + c); bb1[i] = __ldg(Bt + (kk + 1) * 64 + c); }
        else        { bb0[i] = __ldg(Bh + kk * 32 + c - 64); bb1[i] = __ldg(Bh + (kk + 1) * 32 + c - 64); }
      }
    }
#pragma unroll
    for (int ks = 0; ks < 2; ks++) {
      const int kb = ks * 8;
      uint2 a2[2][4];
#pragma unroll
      for (int mt = 0; mt < 2; mt++) {
        int ar = wr * 32 + mt * 16 + qid;
        a2[mt][0] = AsP[kb + qtid][ar];
        a2[mt][1] = AsP[kb + qtid][ar + 8];
        a2[mt][2] = AsP[kb + qtid + 4][ar];
        a2[mt][3] = AsP[kb + qtid + 4][ar + 8];
      }
#pragma unroll
      for (int nt = 0; nt < 6; nt++) {
        int bn = wc * 48 + nt * 8 + qid;
        uint2 b0 = BsP[kb + qtid][bn];
        uint2 b1 = BsP[kb + qtid + 4][bn];
        uint32_t bhv[2] = {b0.x, b1.x};
        uint32_t blv[2] = {b0.y, b1.y};
#pragma unroll
        for (int mt = 0; mt < 2; mt++) {
          uint32_t ah[4] = {a2[mt][0].x, a2[mt][1].x, a2[mt][2].x, a2[mt][3].x};
          uint32_t al[4] = {a2[mt][0].y, a2[mt][1].y, a2[mt][2].y, a2[mt][3].y};
          mma16(acc[mt][nt], ah, bhv);
          mma16(acc[mt][nt], ah, blv);
          mma16(acc[mt][nt], al, bhv);
        }
      }
    }
    __syncthreads();
  }

#pragma unroll
  for (int mt = 0; mt < 2; mt++) {
    int gr = row0 + wr * 32 + mt * 16 + qid;
#pragma unroll
    for (int nt = 0; nt < 6; nt++) {
      int cc = wc * 48 + nt * 8 + 2 * qtid;
      if (gr < NITEMS) {
        if (cc < 64) { Cf[gr * 64 + cc] = acc[mt][nt][0]; Cf[gr * 64 + cc + 1] = acc[mt][nt][1]; }
        else         { Cl[gr * 32 + cc - 64] = acc[mt][nt][0]; Cl[gr * 32 + cc - 63] = acc[mt][nt][1]; }
      }
      if (gr + 8 < NITEMS) {
        if (cc < 64) { Cf[(gr + 8) * 64 + cc] = acc[mt][nt][2]; Cf[(gr + 8) * 64 + cc + 1] = acc[mt][nt][3]; }
        else         { Cl[(gr + 8) * 32 + cc - 64] = acc[mt][nt][2]; Cl[(gr + 8) * 32 + cc - 63] = acc[mt][nt][3]; }
      }
    }
  }
}

// ================= CSR scans (3 parallel launches — measured faster than chained) =================
__global__ void csr_chunksum2(const int* __restrict__ cntA, const int* __restrict__ cntB,
                              int* __restrict__ csumA, int* __restrict__ csumB,
                              int nA, int nB) {
  __shared__ int ts[256];
  const int* cnt;
  int* csum;
  int n, ch;
  if (blockIdx.x < NCHA) { cnt = cntA; csum = csumA; n = nA; ch = blockIdx.x; }
  else                   { cnt = cntB; csum = csumB; n = nB; ch = blockIdx.x - NCHA; }
  int base = ch * 1024;
  int s = 0;
  for (int i = threadIdx.x; i < 1024; i += 256) {
    int idx = base + i;
    s += (idx < n) ? cnt[idx] : 0;
  }
  ts[threadIdx.x] = s;
  __syncthreads();
  for (int off = 128; off; off >>= 1) {
    if (threadIdx.x < off) ts[threadIdx.x] += ts[threadIdx.x + off];
    __syncthreads();
  }
  if (threadIdx.x == 0) csum[ch] = ts[0];
}

__global__ void csr_scanchunks2(const int* __restrict__ csumA, int* __restrict__ coffA,
                                int* __restrict__ startA,
                                const int* __restrict__ csumB, int* __restrict__ coffB,
                                int* __restrict__ startB) {
  if (threadIdx.x != 0) return;
  if (blockIdx.x == 0) {
    int run = 0;
    for (int i = 0; i < NCHA; i++) { coffA[i] = run; run += csumA[i]; }
    startA[NNODES] = NNZADJ;
  } else {
    int run = 0;
    for (int i = 0; i < NCHR; i++) { coffB[i] = run; run += csumB[i]; }
    startB[NUSERS] = NNZR;
  }
}

__global__ void csr_chunkscan2(int* __restrict__ cntA, const int* __restrict__ coffA,
                               int* __restrict__ curA,
                               int* __restrict__ cntB, const int* __restrict__ coffB,
                               int* __restrict__ curB, int nA, int nB) {
  __shared__ int sm[1024];
  __shared__ int ts[256];
  int* cnt;
  const int* coff;
  int* cur;
  int n, ch;
  if (blockIdx.x < NCHA) { cnt = cntA; coff = coffA; cur = curA; n = nA; ch = blockIdx.x; }
  else                   { cnt = cntB; coff = coffB; cur = curB; n = nB; ch = blockIdx.x - NCHA; }
  int base = ch * 1024;
  for (int i = threadIdx.x; i < 1024; i += 256)
    sm[i] = (base + i < n) ? cnt[base + i] : 0;
  __syncthreads();
  int t = threadIdx.x;
  int a0 = sm[t * 4], a1 = sm[t * 4 + 1], a2 = sm[t * 4 + 2], a3 = sm[t * 4 + 3];
  int local = a0 + a1 + a2 + a3;
  ts[t] = local;
  __syncthreads();
  for (int off = 1; off < 256; off <<= 1) {
    int v = (t >= off) ? ts[t - off] : 0;
    __syncthreads();
    ts[t] += v;
    __syncthreads();
  }
  int excl = ts[t] - local + coff[ch];
  int i0 = base + t * 4;
  if (i0 + 0 < n) { cnt[i0 + 0] = excl;                cur[i0 + 0] = excl; }
  if (i0 + 1 < n) { cnt[i0 + 1] = excl + a0;           cur[i0 + 1] = excl + a0; }
  if (i0 + 2 < n) { cnt[i0 + 2] = excl + a0 + a1;      cur[i0 + 2] = excl + a0 + a1; }
  if (i0 + 3 < n) { cnt[i0 + 3] = excl + a0 + a1 + a2; cur[i0 + 3] = excl + a0 + a1 + a2; }
}

__global__ void csr_scatter2(const int* __restrict__ rowsA, const int* __restrict__ colsA,
                             const float* __restrict__ valsA, int* __restrict__ curA,
                             int* __restrict__ scolA, float* __restrict__ svalA,
                             const int* __restrict__ rowsB, const int* __restrict__ colsB,
                             const float* __restrict__ valsB, int* __restrict__ curB,
                             int* __restrict__ scolB, float* __restrict__ svalB) {
  int b = blockIdx.x;
  if (b < GADJE) {
    int e = b * 256 + threadIdx.x;
    if (e >= NNZADJ) return;
    int r = __ldg(rowsA + e);
    int p = atomicAdd(&curA[r], 1);
    scolA[p] = __ldg(colsA + e);
    svalA[p] = __ldg(valsA + e);
  } else {
    int e = (b - GADJE) * 256 + threadIdx.x;
    if (e >= NNZR) return;
    int r = __ldg(rowsB + e);
    int p = atomicAdd(&curB[r], 1);
    scolB[p] = __ldg(colsB + e);
    svalB[p] = __ldg(valsB + e);
  }
}

// ================= phase 2: r_fused + gumbel-items + cge1(bf16 out) =================
__global__ void phase2_kernel(const int* __restrict__ startR, const int* __restrict__ scolR,
                              const float* __restrict__ svalR,
                              const float* __restrict__ ihl0, const float* __restrict__ ihl1,
                              const float2* __restrict__ itf0, const float2* __restrict__ itf1,
                              float* __restrict__ uhl0, float* __restrict__ uhl1,
                              float2* __restrict__ m00, float2* __restrict__ m01,
                              float* __restrict__ ih0, float* __restrict__ ih1,
                              unsigned ki00, unsigned ki01, unsigned ki10, unsigned ki11,
                              const int* __restrict__ startA, const int* __restrict__ scolA,
                              const float* __restrict__ svalA,
                              const float2* __restrict__ Gu, const float2* __restrict__ Gi,
                              uint32_t* __restrict__ e1h) {
  int bx = blockIdx.x;
  int wid = threadIdx.x >> 5, lane = threadIdx.x & 31;
  if (bx < GUSERB) {
    int row = bx * 8 + wid;
    if (row >= NUSERS) return;
    const float* xs = blockIdx.y ? ihl1 : ihl0;
    const float2* xd = blockIdx.y ? itf1 : itf0;
    float* ys = blockIdx.y ? uhl1 : uhl0;
    float2* yd = blockIdx.y ? m01 : m00;
    int s = startR[row], e = startR[row + 1];
    float a = 0.f, ax = 0.f, ay = 0.f;
    int i = s;
    for (; i + 1 < e; i += 2) {
      int c0 = __ldg(scolR + i), c1 = __ldg(scolR + i + 1);
      float v0 = __ldg(svalR + i), v1 = __ldg(svalR + i + 1);
      float s0 = __ldg(xs + (size_t)c0 * 32 + lane);
      float s1 = __ldg(xs + (size_t)c1 * 32 + lane);
      float2 d0 = __ldg(xd + (size_t)c0 * 32 + lane);
      float2 d1 = __ldg(xd + (size_t)c1 * 32 + lane);
      a = fmaf(v0, s0, a); ax = fmaf(v0, d0.x, ax); ay = fmaf(v0, d0.y, ay);
      a = fmaf(v1, s1, a); ax = fmaf(v1, d1.x, ax); ay = fmaf(v1, d1.y, ay);
    }
    for (; i < e; i++) {
      int c = __ldg(scolR + i);
      float v = __ldg(svalR + i);
      a = fmaf(v, __ldg(xs + (size_t)c * 32 + lane), a);
      float2 d = __ldg(xd + (size_t)c * 32 + lane);
      ax = fmaf(v, d.x, ax); ay = fmaf(v, d.y, ay);
    }
    ys[(size_t)row * 32 + lane] = a;
    yd[(size_t)row * 32 + lane] = make_float2(ax, ay);
  } else if (bx < GUSERB + GITMB) {
    int row = (bx - GUSERB) * 8 + wid;
    if (row >= NITEMS) return;
    const float* lg = blockIdx.y ? ihl1 : ihl0;
    float* o = blockIdx.y ? ih1 : ih0;
    unsigned k0 = blockIdx.y ? ki10 : ki00;
    unsigned k1 = blockIdx.y ? ki11 : ki01;
    gumbel_row(lg, o, row, lane, k0, k1);
  } else {
    int row = ((bx - GUSERB - GITMB) + blockIdx.y * GCGEB) * 8 + wid;
    if (row >= NNODES) return;
    int s = startA[row], e = startA[row + 1];
    float ax = 0.f, ay = 0.f;
    int i = s;
    for (; i + 1 < e; i += 2) {
      int c0 = __ldg(scolA + i), c1 = __ldg(scolA + i + 1);
      float v0 = __ldg(svalA + i), v1 = __ldg(svalA + i + 1);
      const float2* x0p = (c0 < NUSERS) ? Gu + (size_t)c0 * 32 : Gi + (size_t)(c0 - NUSERS) * 32;
      const float2* x1p = (c1 < NUSERS) ? Gu + (size_t)c1 * 32 : Gi + (size_t)(c1 - NUSERS) * 32;
      float2 x0 = __ldg(x0p + lane), x1 = __ldg(x1p + lane);
      ax = fmaf(v0, x0.x, ax); ay = fmaf(v0, x0.y, ay);
      ax = fmaf(v1, x1.x, ax); ay = fmaf(v1, x1.y, ay);
    }
    for (; i < e; i++) {
      int c = __ldg(scolA + i);
      float v = __ldg(svalA + i);
      const float2* xp = (c < NUSERS) ? Gu + (size_t)c * 32 : Gi + (size_t)(c - NUSERS) * 32;
      float2 xv = __ldg(xp + lane);
      ax = fmaf(v, xv.x, ax); ay = fmaf(v, xv.y, ay);
    }
    e1h[(size_t)row * 32 + lane] = bf16pack(ax, ay);
  }
}

// ================= phase 3: mega adj pass (cge2+combine, mge both) + gumbel-u =================
__global__ void phase3_kernel(const int* __restrict__ startA, const int* __restrict__ scolA,
                              const float* __restrict__ svalA,
                              const uint32_t* __restrict__ e1h,
                              const float2* __restrict__ Gu, const float2* __restrict__ Gi,
                              float2* __restrict__ cge,
                              const float2* __restrict__ m00, const float2* __restrict__ m01,
                              const float2* __restrict__ itf0, const float2* __restrict__ itf1,
                              const float* __restrict__ inv,
                              float2* __restrict__ m10, float2* __restrict__ m11,
                              const float* __restrict__ uhl0, const float* __restrict__ uhl1,
                              float* __restrict__ uh0, float* __restrict__ uh1,
                              unsigned ku00, unsigned ku01, unsigned ku10, unsigned ku11) {
  int bx = blockIdx.x;
  int wid = threadIdx.x >> 5, lane = threadIdx.x & 31;
  if (bx < GNODEB) {
    int row = bx * 8 + wid;
    if (row >= NNODES) return;
    int s = startA[row], e = startA[row + 1];
    float ex = 0.f, ey = 0.f;
    float vx = 0.f, vy = 0.f;
    float tx = 0.f, ty = 0.f;
    int i = s;
    for (; i + 1 < e; i += 2) {
      int c0 = __ldg(scolA + i), c1 = __ldg(scolA + i + 1);
      float v0 = __ldg(svalA + i), v1 = __ldg(svalA + i + 1);
      uint32_t u0 = __ldg(e1h + (size_t)c0 * 32 + lane);
      uint32_t u1 = __ldg(e1h + (size_t)c1 * 32 + lane);
      float vm0 = v0, vm1 = v1;
      const float2 *sv0, *st0, *sv1, *st1;
      if (c0 < NUSERS) { vm0 = v0 * __ldg(inv + c0); sv0 = m00 + (size_t)c0 * 32; st0 = m01 + (size_t)c0 * 32; }
      else             { sv0 = itf0 + (size_t)(c0 - NUSERS) * 32; st0 = itf1 + (size_t)(c0 - NUSERS) * 32; }
      if (c1 < NUSERS) { vm1 = v1 * __ldg(inv + c1); sv1 = m00 + (size_t)c1 * 32; st1 = m01 + (size_t)c1 * 32; }
      else             { sv1 = itf0 + (size_t)(c1 - NUSERS) * 32; st1 = itf1 + (size_t)(c1 - NUSERS) * 32; }
      float2 dv0 = __ldg(sv0 + lane), dt0 = __ldg(st0 + lane);
      float2 dv1 = __ldg(sv1 + lane), dt1 = __ldg(st1 + lane);
      float2 ev0 = bf16unpack(u0), ev1 = bf16unpack(u1);
      ex = fmaf(v0, ev0.x, ex); ey = fmaf(v0, ev0.y, ey);
      vx = fmaf(vm0, dv0.x, vx); vy = fmaf(vm0, dv0.y, vy);
      tx = fmaf(vm0, dt0.x, tx); ty = fmaf(vm0, dt0.y, ty);
      ex = fmaf(v1, ev1.x, ex); ey = fmaf(v1, ev1.y, ey);
      vx = fmaf(vm1, dv1.x, vx); vy = fmaf(vm1, dv1.y, vy);
      tx = fmaf(vm1, dt1.x, tx); ty = fmaf(vm1, dt1.y, ty);
    }
    for (; i < e; i++) {
      int c = __ldg(scolA + i);
      float v = __ldg(svalA + i);
      float2 ev = bf16unpack(__ldg(e1h + (size_t)c * 32 + lane));
      float vm = v;
      const float2 *sv, *st;
      if (c < NUSERS) { vm = v * __ldg(inv + c); sv = m00 + (size_t)c * 32; st = m01 + (size_t)c * 32; }
      else            { sv = itf0 + (size_t)(c - NUSERS) * 32; st = itf1 + (size_t)(c - NUSERS) * 32; }
      float2 dv = __ldg(sv + lane), dt = __ldg(st + lane);
      ex = fmaf(v, ev.x, ex); ey = fmaf(v, ev.y, ey);
      vx = fmaf(vm, dv.x, vx); vy = fmaf(vm, dv.y, vy);
      tx = fmaf(vm, dt.x, tx); ty = fmaf(vm, dt.y, ty);
    }
    float2 ego = (row < NUSERS) ? __ldg(Gu + (size_t)row * 32 + lane)
                                : __ldg(Gi + (size_t)(row - NUSERS) * 32 + lane);
    float2 e1v = bf16unpack(e1h[(size_t)row * 32 + lane]);
    cge[(size_t)row * 32 + lane] = make_float2((ego.x + e1v.x + ex) * (1.0f / 3.0f),
                                               (ego.y + e1v.y + ey) * (1.0f / 3.0f));
    m10[(size_t)row * 32 + lane] = make_float2(vx, vy);
    m11[(size_t)row * 32 + lane] = make_float2(tx, ty);
  } else if (bx < GNODEB + GUSERB) {
    int row = (bx - GNODEB) * 8 + wid;
    if (row >= NUSERS) return;
    gumbel_row(uhl0, uh0, row, lane, ku00, ku01);
  } else {
    int row = (bx - GNODEB - GUSERB) * 8 + wid;
    if (row >= NUSERS) return;
    gumbel_row(uhl1, uh1, row, lane, ku10, ku11);
  }
}

// ---------------- lat[32,64] += ih^T @ icge, both modalities (lat pre-zeroed) ----------------
__global__ void lat_both_kernel(const float* __restrict__ w0, const float* __restrict__ w1,
                                const float* __restrict__ icge,
                                float* __restrict__ lat0, float* __restrict__ lat1, int chunk) {
  const float* w = blockIdx.y ? w1 : w0;
  float* lat = blockIdx.y ? lat1 : lat0;
  int lane = threadIdx.x & 31;
  int kg = threadIdx.x >> 5;
  int start = blockIdx.x * chunk;
  int end = min(start + chunk, NITEMS);
  float acc[8] = {0, 0, 0, 0, 0, 0, 0, 0};
  for (int it = start; it < end; ++it) {
    float wv = w[it * HH + lane];
    const float* cr = icge + it * EK + kg * 8;
#pragma unroll
    for (int j = 0; j < 8; j++) acc[j] = fmaf(wv, __ldg(cr + j), acc[j]);
  }
#pragma unroll
  for (int j = 0; j < 8; j++) atomicAdd(&lat[lane * EK + kg * 8 + j], acc[j]);
}

// ---------------- fused hyper-apply + final, warp per row ----------------
#define OI   (NUSERS * EK)
#define OHVU ((NUSERS + NITEMS) * EK)
#define OHVI (OHVU + NUSERS * EK)
#define OHTU (OHVI + NITEMS * EK)
#define OHTI (OHTU + NUSERS * EK)
__global__ void final_fused(float* __restrict__ out, const float* __restrict__ cge,
                            const float* __restrict__ m1a, const float* __restrict__ m1b,
                            const float* __restrict__ ih0, const float* __restrict__ ih1,
                            const float* __restrict__ uh0, const float* __restrict__ uh1,
                            const float* __restrict__ lat0, const float* __restrict__ lat1) {
  __shared__ float slA[HH * EK];
  __shared__ float slB[HH * EK];
  for (int t = threadIdx.x; t < HH * EK; t += 256) { slA[t] = lat0[t]; slB[t] = lat1[t]; }
  __syncthreads();
  int row = blockIdx.x * 8 + (threadIdx.x >> 5);
  if (row >= NNODES) return;
  int lane = threadIdx.x & 31;
  const float* w0;
  const float* w1;
  float *outV, *outT, *dst;
  if (row < NUSERS) {
    w0 = uh0 + row * HH; w1 = uh1 + row * HH;
    outV = out + OHVU + row * EK; outT = out + OHTU + row * EK;
    dst = out + row * EK;
  } else {
    int ir = row - NUSERS;
    w0 = ih0 + ir * HH; w1 = ih1 + ir * HH;
    outV = out + OHVI + ir * EK; outT = out + OHTI + ir * EK;
    dst = out + OI + ir * EK;
  }
  float wl0 = w0[lane], wl1 = w1[lane];
  float s0 = 0.f, s1 = 0.f, t0 = 0.f, t1 = 0.f;
#pragma unroll
  for (int h = 0; h < HH; h++) {
    float wv0 = __shfl_sync(0xffffffffu, wl0, h);
    float wv1 = __shfl_sync(0xffffffffu, wl1, h);
    s0 = fmaf(wv0, slA[h * EK + lane], s0);
    s1 = fmaf(wv0, slA[h * EK + lane + 32], s1);
    t0 = fmaf(wv1, slB[h * EK + lane], t0);
    t1 = fmaf(wv1, slB[h * EK + lane + 32], t1);
  }
  outV[lane] = s0; outV[lane + 32] = s1;
  outT[lane] = t0; outT[lane + 32] = t1;
  int b = row * EK;
  float a0 = m1a[b + lane], a1 = m1a[b + lane + 32];
  float c0 = m1b[b + lane], c1 = m1b[b + lane + 32];
  float g0 = s0 + t0, g1 = s1 + t1;
  float sa = a0 * a0 + a1 * a1;
  float sc = c0 * c0 + c1 * c1;
  float sg = g0 * g0 + g1 * g1;
#pragma unroll
  for (int s = 16; s; s >>= 1) {
    sa += __shfl_xor_sync(0xffffffffu, sa, s);
    sc += __shfl_xor_sync(0xffffffffu, sc, s);
    sg += __shfl_xor_sync(0xffffffffu, sg, s);
  }
  float ia = 1.0f / fmaxf(sqrtf(sa), 1e-12f);
  float ic = 1.0f / fmaxf(sqrtf(sc), 1e-12f);
  float ig = 0.2f / fmaxf(sqrtf(sg), 1e-12f);
  dst[lane]      = cge[b + lane]      + a0 * ia + c0 * ic + g0 * ig;
  dst[lane + 32] = cge[b + lane + 32] + a1 * ia + c1 * ic + g1 * ig;
}

// ================================================================================
extern "C" void kernel_launch(void* const* d_in, const int* in_sizes, int n_in,
                              void* d_out, int out_size) {
  const float* Gu       = (const float*)d_in[0];
  const float* Gi       = (const float*)d_in[1];
  const float* feat_v   = (const float*)d_in[2];
  const float* feat_t   = (const float*)d_in[3];
  const float* trs_v    = (const float*)d_in[4];
  const float* trs_t    = (const float*)d_in[5];
  const float* hyp_v    = (const float*)d_in[6];
  const float* hyp_t    = (const float*)d_in[7];
  const float* inv      = (const float*)d_in[8];
  const float* adj_vals = (const float*)d_in[9];
  const float* r_vals   = (const float*)d_in[10];
  const int*   adj_rows = (const int*)d_in[11];
  const int*   adj_cols = (const int*)d_in[12];
  const int*   r_rows   = (const int*)d_in[13];
  const int*   r_cols   = (const int*)d_in[14];
  float* out = (float*)d_out;
  int Fv = in_sizes[2] / NITEMS;
  int Ft = in_sizes[3] / NITEMS;

  float *p_itf, *p_ihl, *p_uhl, *p_ih, *p_uh, *p_e0, *p_m0, *p_m1, *p_lat;
  uint32_t* p_e1h;
  int *p_hist, *pA_cur, *pA_scol, *pA_csum, *pA_coff;
  int *pR_cur, *pR_scol, *pR_csum, *pR_coff;
  float *pA_sval, *pR_sval;
  cudaGetSymbolAddress((void**)&p_itf, g_itf);
  cudaGetSymbolAddress((void**)&p_ihl, g_ihl);
  cudaGetSymbolAddress((void**)&p_uhl, g_uhl);
  cudaGetSymbolAddress((void**)&p_ih,  g_ih);
  cudaGetSymbolAddress((void**)&p_uh,  g_uh);
  cudaGetSymbolAddress((void**)&p_e0,  g_e0);
  cudaGetSymbolAddress((void**)&p_e1h, g_e1h);
  cudaGetSymbolAddress((void**)&p_m0,  g_m0);
  cudaGetSymbolAddress((void**)&p_m1,  g_m1);
  cudaGetSymbolAddress((void**)&p_lat, g_lat);
  cudaGetSymbolAddress((void**)&p_hist, g_hist);
  cudaGetSymbolAddress((void**)&pA_cur,  g_curA);
  cudaGetSymbolAddress((void**)&pA_scol, g_scolA);
  cudaGetSymbolAddress((void**)&pA_sval, g_svalA);
  cudaGetSymbolAddress((void**)&pA_csum, g_csumA);
  cudaGetSymbolAddress((void**)&pA_coff, g_coffA);
  cudaGetSymbolAddress((void**)&pR_cur,  g_curR);
  cudaGetSymbolAddress((void**)&pR_scol, g_scolR);
  cudaGetSymbolAddress((void**)&pR_sval, g_svalR);
  cudaGetSymbolAddress((void**)&pR_csum, g_csumR);
  cudaGetSymbolAddress((void**)&pR_coff, g_coffR);
  int* pA_start = p_hist;
  int* pR_start = p_hist + NNODES + 1;
  float* p_itfT = p_itf + NITEMS * EK;
  float* p_ihlT = p_ihl + NITEMS * HH;
  float* p_uhlT = p_uhl + NUSERS * HH;
  float* p_ihT  = p_ih + NITEMS * HH;
  float* p_uhT  = p_uh + NUSERS * HH;
  float* p_m0T  = p_m0 + NUSERS * EK;
  float* p_m1T  = p_m1 + NNODES * EK;
  float* p_latT = p_lat + HH * EK;

  // JAX threefry keys
  uint32_t ki0[2], ki1[2], ku0[2], ku1[2];
  for (int m = 0; m < 2; m++) {
    uint32_t km0, km1;
    tf2x32(0u, 42u, 0u, (uint32_t)m, &km0, &km1);
    tf2x32(km0, km1, 0u, 0u, &ki0[m], &ki1[m]);
    tf2x32(km0, km1, 0u, 1u, &ku0[m], &ku1[m]);
  }

  // ---- zero CSR histograms (one memset) + lat ----
  cudaMemsetAsync(p_hist, 0, HIST_TOTAL * sizeof(int), 0);
  cudaMemsetAsync(p_lat, 0, 2 * HH * EK * sizeof(float), 0);

  // ---- GEMMs + CSR histograms in one launch ----
  gemm_hist_kernel<<<dim3(GEMMB + GADJE, 2), 256>>>(
      feat_v, feat_t, trs_v, trs_t, hyp_v, hyp_t,
      p_itf, p_itfT, p_ihl, p_ihlT, Fv, Ft,
      adj_rows, r_rows, pA_start, pR_start);

  // ---- CSR scans (3 parallel launches) + scatter ----
  csr_chunksum2<<<NCHA + NCHR, 256>>>(pA_start, pR_start, pA_csum, pR_csum, NNODES, NUSERS);
  csr_scanchunks2<<<2, 32>>>(pA_csum, pA_coff, pA_start, pR_csum, pR_coff, pR_start);
  csr_chunkscan2<<<NCHA + NCHR, 256>>>(pA_start, pA_coff, pA_cur,
                                       pR_start, pR_coff, pR_cur, NNODES, NUSERS);
  csr_scatter2<<<GADJE + GRE, 256>>>(adj_rows, adj_cols, adj_vals, pA_cur, pA_scol, pA_sval,
                                     r_rows, r_cols, r_vals, pR_cur, pR_scol, pR_sval);

  // ---- phase 2: r_fused + gumbel-items + cge1 ----
  phase2_kernel<<<dim3(GUSERB + GITMB + GCGEB, 2), 256>>>(
      pR_start, pR_scol, pR_sval,
      p_ihl, p_ihlT, (const float2*)p_itf, (const float2*)p_itfT,
      p_uhl, p_uhlT, (float2*)p_m0, (float2*)p_m0T,
      p_ih, p_ihT, ki0[0], ki1[0], ki0[1], ki1[1],
      pA_start, pA_scol, pA_sval,
      (const float2*)Gu, (const float2*)Gi, p_e1h);

  // ---- phase 3: mega adj (cge2 + mge both) + gumbel-u ----
  phase3_kernel<<<GNODEB + 2 * GUSERB, 256>>>(
      pA_start, pA_scol, pA_sval, p_e1h,
      (const float2*)Gu, (const float2*)Gi, (float2*)p_e0,
      (const float2*)p_m0, (const float2*)p_m0T,
      (const float2*)p_itf, (const float2*)p_itfT, inv,
      (float2*)p_m1, (float2*)p_m1T,
      p_uhl, p_uhlT, p_uh, p_uhT, ku0[0], ku1[0], ku0[1], ku1[1]);

  // ---- hyper path + final ----
  lat_both_kernel<<<dim3(120, 2), 256>>>(p_ih, p_ihT, p_e0 + NUSERS * EK, p_lat, p_latT, 250);
  final_fused<<<GNODEB, 256>>>(out, p_e0, p_m1, p_m1T,
                               p_ih, p_ihT, p_uh, p_uhT, p_lat, p_latT);
}

// round 15
// speedup vs baseline: 1.0750x; 1.0294x over previous
#include <cuda_runtime.h>
#include <stdint.h>

#define NUSERS 50000
#define NITEMS 30000
#define NNODES 80000
#define EK 64
#define HH 32
#define NNZADJ 2000000
#define NNZR 1000000
#define NCHA ((NNODES + 1023) / 1024)
#define NCHR ((NUSERS + 1023) / 1024)
#define GEMMB 235                       // (NITEMS+127)/128
#define GADJE ((NNZADJ + 255) / 256)
#define GRE   ((NNZR + 255) / 256)
#define GUSERB ((NUSERS + 7) / 8)       // 6250
#define GITMB  ((NITEMS + 7) / 8)       // 3750
#define GNODEB ((NNODES + 7) / 8)       // 10000

// ---------------- scratch (device globals; allocation is forbidden) ----------------
__device__ float4 g_itfc[NITEMS * 32];       // item feats, interleaved fp32 {mod0.xy, mod1.xy}
__device__ float g_ihl[2][NITEMS * HH];      // hyper logits (fp32; feeds gumbel)
__device__ float g_uhl[2][NUSERS * HH];
__device__ float g_ih[2][NITEMS * HH];
__device__ float g_uh[2][NUSERS * HH];
__device__ float g_e0[NNODES * EK];          // cge (fp32)
__device__ uint32_t g_e1h[NNODES * 32];      // e1 as bf16x2 per lane-pair (damped path: safe)
__device__ float4 g_m0c[NUSERS * 32];        // m0 interleaved fp32 {mod0.xy, mod1.xy}
__device__ float g_m1[2][NNODES * EK];
__device__ float g_lat[2][HH * EK];
// CSR scratch: histA and histR in ONE buffer (single memset)
#define HIST_TOTAL (NNODES + 1 + NUSERS + 1)
__device__ int   g_hist[HIST_TOTAL];
__device__ int   g_curA[NNODES];
__device__ int2  g_scvA[NNZADJ];             // packed {col, val-bits}
__device__ int   g_csumA[NCHA];
__device__ int   g_coffA[NCHA];
__device__ int   g_curR[NUSERS];
__device__ int2  g_scvR[NNZR];
__device__ int   g_csumR[NCHR];
__device__ int   g_coffR[NCHR];

// ---------------- threefry2x32 (JAX-compatible, 20 rounds) ----------------
__host__ __device__ __forceinline__ void tf2x32(uint32_t k0, uint32_t k1,
                                                uint32_t x0, uint32_t x1,
                                                uint32_t* o0, uint32_t* o1) {
  uint32_t ks2 = k0 ^ k1 ^ 0x1BD11BDAu;
  uint32_t v0 = x0 + k0, v1 = x1 + k1;
#define TFR(r) { v0 += v1; v1 = (v1 << (r)) | (v1 >> (32 - (r))); v1 ^= v0; }
  TFR(13) TFR(15) TFR(26) TFR(6)
  v0 += k1;  v1 += ks2 + 1u;
  TFR(17) TFR(29) TFR(16) TFR(24)
  v0 += ks2; v1 += k0 + 2u;
  TFR(13) TFR(15) TFR(26) TFR(6)
  v0 += k0;  v1 += k1 + 3u;
  TFR(17) TFR(29) TFR(16) TFR(24)
  v0 += k1;  v1 += ks2 + 4u;
  TFR(13) TFR(15) TFR(26) TFR(6)
  v0 += ks2; v1 += k0 + 5u;
#undef TFR
  *o0 = v0; *o1 = v1;
}

// ---------------- bf16 pack/unpack + mma helpers ----------------
__device__ __forceinline__ uint2 bf16split2(float x0, float x1) {
  uint32_t h;
  asm("cvt.rn.bf16x2.f32 %0, %1, %2;" : "=r"(h) : "f"(x1), "f"(x0));
  float h0 = __uint_as_float(h << 16);
  float h1 = __uint_as_float(h & 0xFFFF0000u);
  uint32_t l;
  asm("cvt.rn.bf16x2.f32 %0, %1, %2;" : "=r"(l) : "f"(x1 - h1), "f"(x0 - h0));
  return make_uint2(h, l);
}
__device__ __forceinline__ uint32_t bf16pack(float x0, float x1) {
  uint32_t h;
  asm("cvt.rn.bf16x2.f32 %0, %1, %2;" : "=r"(h) : "f"(x1), "f"(x0));
  return h;
}
__device__ __forceinline__ float2 bf16unpack(uint32_t u) {
  return make_float2(__uint_as_float(u << 16), __uint_as_float(u & 0xFFFF0000u));
}

__device__ __forceinline__ void mma16(float* c, const uint32_t* a, const uint32_t* b) {
  asm volatile("mma.sync.aligned.m16n8k16.row.col.f32.bf16.bf16.f32 "
               "{%0,%1,%2,%3}, {%4,%5,%6,%7}, {%8,%9}, {%0,%1,%2,%3};"
               : "+f"(c[0]), "+f"(c[1]), "+f"(c[2]), "+f"(c[3])
               : "r"(a[0]), "r"(a[1]), "r"(a[2]), "r"(a[3]), "r"(b[0]), "r"(b[1]));
}

// ---------------- gumbel softmax row helper ----------------
__device__ __forceinline__ void gumbel_row(const float* __restrict__ logits,
                                           float* __restrict__ out,
                                           int row, int lane, unsigned k0, unsigned k1) {
  unsigned idx = (unsigned)row * 32u + (unsigned)lane;
  unsigned b0, b1;
  tf2x32(k0, k1, 0u, idx, &b0, &b1);
  unsigned bits = b0 ^ b1;
  float f = __uint_as_float((bits >> 9) | 0x3f800000u) - 1.0f;
  const float TINY = 1.1754943508222875e-38f;
  float u = fmaxf(TINY, f + TINY);
  float g = -logf(-logf(u));
  float z = (logits[row * 32 + lane] + g) * 5.0f;
  float mx = z;
#pragma unroll
  for (int s = 16; s; s >>= 1) mx = fmaxf(mx, __shfl_xor_sync(0xffffffffu, mx, s));
  float e = expf(z - mx);
  float sm = e;
#pragma unroll
  for (int s = 16; s; s >>= 1) sm += __shfl_xor_sync(0xffffffffu, sm, s);
  out[row * 32 + lane] = e / sm;
}

// ================= fused GEMM(bf16x3) + CSR histogram, one launch =================
// GEMM writes item feats into interleaved fp32 itfc (each modality its float2 half).
#define ASP 132
#define BSP 100
__global__ __launch_bounds__(256, 2)
void gemm_hist_kernel(const float* __restrict__ A0, const float* __restrict__ A1,
                      const float* __restrict__ Bt0, const float* __restrict__ Bt1,
                      const float* __restrict__ Bh0, const float* __restrict__ Bh1,
                      float2* __restrict__ itfc2,
                      float* __restrict__ Cl0, float* __restrict__ Cl1,
                      int F0, int F1,
                      const int* __restrict__ rowsA, const int* __restrict__ rowsR,
                      int* __restrict__ cntA, int* __restrict__ cntR) {
  if (blockIdx.x >= GEMMB) {
    int hb = blockIdx.x - GEMMB;
    if (blockIdx.y == 0) {
      int e = hb * 256 + threadIdx.x;
      if (e < NNZADJ) atomicAdd(&cntA[__ldg(rowsA + e)], 1);
    } else {
      if (hb < GRE) {
        int e = hb * 256 + threadIdx.x;
        if (e < NNZR) atomicAdd(&cntR[__ldg(rowsR + e)], 1);
      }
    }
    return;
  }
  __shared__ uint2 AsP[16][ASP];
  __shared__ uint2 BsP[16][BSP];
  const int mmod = blockIdx.y;
  const float* A  = mmod ? A1 : A0;
  const float* Bt = mmod ? Bt1 : Bt0;
  const float* Bh = mmod ? Bh1 : Bh0;
  float* Cl = mmod ? Cl1 : Cl0;
  const int F = mmod ? F1 : F0;

  const int row0 = blockIdx.x * 128;
  const int tid = threadIdx.x;
  const int wid = tid >> 5, lane = tid & 31;
  const int wr = wid >> 1, wc = wid & 1;
  const int qid = lane >> 2, qtid = lane & 3;

  const int lr = tid >> 1;
  const int lk2 = (tid & 1) * 8;
  const int gr_l = row0 + lr;
  const bool rok = gr_l < NITEMS;
  const float* Arow = A + (size_t)gr_l * F + lk2 * 2;

  float4 a4[4];
  float bb0[6], bb1[6];
  const float4 z4 = make_float4(0.f, 0.f, 0.f, 0.f);
#pragma unroll
  for (int i = 0; i < 4; i++) a4[i] = rok ? __ldg((const float4*)(Arow + 4 * i)) : z4;
#pragma unroll
  for (int i = 0; i < 6; i++) {
    int p = tid + 256 * i, k2 = p / 96, c = p - k2 * 96;
    int kk = 2 * k2;
    if (c < 64) { bb0[i] = __ldg(Bt + kk * 64 + c); bb1[i] = __ldg(Bt + (kk + 1) * 64 + c); }
    else        { bb0[i] = __ldg(Bh + kk * 32 + c - 64); bb1[i] = __ldg(Bh + (kk + 1) * 32 + c - 64); }
  }

  float acc[2][6][4];
#pragma unroll
  for (int mt = 0; mt < 2; mt++)
#pragma unroll
    for (int nt = 0; nt < 6; nt++)
#pragma unroll
      for (int j = 0; j < 4; j++) acc[mt][nt][j] = 0.0f;

  for (int k0 = 0; k0 < F; k0 += 32) {
    float av[16];
#pragma unroll
    for (int i = 0; i < 4; i++) {
      av[4 * i + 0] = a4[i].x; av[4 * i + 1] = a4[i].y;
      av[4 * i + 2] = a4[i].z; av[4 * i + 3] = a4[i].w;
    }
#pragma unroll
    for (int j = 0; j < 8; j++)
      AsP[lk2 + j][lr] = bf16split2(av[2 * j], av[2 * j + 1]);
#pragma unroll
    for (int i = 0; i < 6; i++) {
      int p = tid + 256 * i, k2 = p / 96, c = p - k2 * 96;
      BsP[k2][c] = bf16split2(bb0[i], bb1[i]);
    }
    __syncthreads();
    int kn = k0 + 32;
    if (kn < F) {
#pragma unroll
      for (int i = 0; i < 4; i++) a4[i] = rok ? __ldg((const float4*)(Arow + kn + 4 * i)) : z4;
#pragma unroll
      for (int i = 0; i < 6; i++) {
        int p = tid + 256 * i, k2 = p / 96, c = p - k2 * 96;
        int kk = kn + 2 * k2;
        if (c < 64) { bb0[i] = __ldg(Bt + kk * 64 + c); bb1[i] = __ldg(Bt + (kk + 1) * 64 + c); }
        else        { bb0[i] = __ldg(Bh + kk * 32 + c - 64); bb1[i] = __ldg(Bh + (kk + 1) * 32 + c - 64); }
      }
    }
#pragma unroll
    for (int ks = 0; ks < 2; ks++) {
      const int kb = ks * 8;
      uint2 a2[2][4];
#pragma unroll
      for (int mt = 0; mt < 2; mt++) {
        int ar = wr * 32 + mt * 16 + qid;
        a2[mt][0] = AsP[kb + qtid][ar];
        a2[mt][1] = AsP[kb + qtid][ar + 8];
        a2[mt][2] = AsP[kb + qtid + 4][ar];
        a2[mt][3] = AsP[kb + qtid + 4][ar + 8];
      }
#pragma unroll
      for (int nt = 0; nt < 6; nt++) {
        int bn = wc * 48 + nt * 8 + qid;
        uint2 b0 = BsP[kb + qtid][bn];
        uint2 b1 = BsP[kb + qtid + 4][bn];
        uint32_t bhv[2] = {b0.x, b1.x};
        uint32_t blv[2] = {b0.y, b1.y};
#pragma unroll
        for (int mt = 0; mt < 2; mt++) {
          uint32_t ah[4] = {a2[mt][0].x, a2[mt][1].x, a2[mt][2].x, a2[mt][3].x};
          uint32_t al[4] = {a2[mt][0].y, a2[mt][1].y, a2[mt][2].y, a2[mt][3].y};
          mma16(acc[mt][nt], ah, bhv);
          mma16(acc[mt][nt], ah, blv);
          mma16(acc[mt][nt], al, bhv);
        }
      }
    }
    __syncthreads();
  }

#pragma unroll
  for (int mt = 0; mt < 2; mt++) {
    int gr = row0 + wr * 32 + mt * 16 + qid;
#pragma unroll
    for (int nt = 0; nt < 6; nt++) {
      int cc = wc * 48 + nt * 8 + 2 * qtid;
      if (gr < NITEMS) {
        if (cc < 64) itfc2[((size_t)gr * 32 + (cc >> 1)) * 2 + mmod] = make_float2(acc[mt][nt][0], acc[mt][nt][1]);
        else         { Cl[gr * 32 + cc - 64] = acc[mt][nt][0]; Cl[gr * 32 + cc - 63] = acc[mt][nt][1]; }
      }
      if (gr + 8 < NITEMS) {
        if (cc < 64) itfc2[((size_t)(gr + 8) * 32 + (cc >> 1)) * 2 + mmod] = make_float2(acc[mt][nt][2], acc[mt][nt][3]);
        else         { Cl[(gr + 8) * 32 + cc - 64] = acc[mt][nt][2]; Cl[(gr + 8) * 32 + cc - 63] = acc[mt][nt][3]; }
      }
    }
  }
}

// ================= CSR scans (3 parallel launches) =================
__global__ void csr_chunksum2(const int* __restrict__ cntA, const int* __restrict__ cntB,
                              int* __restrict__ csumA, int* __restrict__ csumB,
                              int nA, int nB) {
  __shared__ int ts[256];
  const int* cnt;
  int* csum;
  int n, ch;
  if (blockIdx.x < NCHA) { cnt = cntA; csum = csumA; n = nA; ch = blockIdx.x; }
  else                   { cnt = cntB; csum = csumB; n = nB; ch = blockIdx.x - NCHA; }
  int base = ch * 1024;
  int s = 0;
  for (int i = threadIdx.x; i < 1024; i += 256) {
    int idx = base + i;
    s += (idx < n) ? cnt[idx] : 0;
  }
  ts[threadIdx.x] = s;
  __syncthreads();
  for (int off = 128; off; off >>= 1) {
    if (threadIdx.x < off) ts[threadIdx.x] += ts[threadIdx.x + off];
    __syncthreads();
  }
  if (threadIdx.x == 0) csum[ch] = ts[0];
}

__global__ void csr_scanchunks2(const int* __restrict__ csumA, int* __restrict__ coffA,
                                int* __restrict__ startA,
                                const int* __restrict__ csumB, int* __restrict__ coffB,
                                int* __restrict__ startB) {
  if (threadIdx.x != 0) return;
  if (blockIdx.x == 0) {
    int run = 0;
    for (int i = 0; i < NCHA; i++) { coffA[i] = run; run += csumA[i]; }
    startA[NNODES] = NNZADJ;
  } else {
    int run = 0;
    for (int i = 0; i < NCHR; i++) { coffB[i] = run; run += csumB[i]; }
    startB[NUSERS] = NNZR;
  }
}

__global__ void csr_chunkscan2(int* __restrict__ cntA, const int* __restrict__ coffA,
                               int* __restrict__ curA,
                               int* __restrict__ cntB, const int* __restrict__ coffB,
                               int* __restrict__ curB, int nA, int nB) {
  __shared__ int sm[1024];
  __shared__ int ts[256];
  int* cnt;
  const int* coff;
  int* cur;
  int n, ch;
  if (blockIdx.x < NCHA) { cnt = cntA; coff = coffA; cur = curA; n = nA; ch = blockIdx.x; }
  else                   { cnt = cntB; coff = coffB; cur = curB; n = nB; ch = blockIdx.x - NCHA; }
  int base = ch * 1024;
  for (int i = threadIdx.x; i < 1024; i += 256)
    sm[i] = (base + i < n) ? cnt[base + i] : 0;
  __syncthreads();
  int t = threadIdx.x;
  int a0 = sm[t * 4], a1 = sm[t * 4 + 1], a2 = sm[t * 4 + 2], a3 = sm[t * 4 + 3];
  int local = a0 + a1 + a2 + a3;
  ts[t] = local;
  __syncthreads();
  for (int off = 1; off < 256; off <<= 1) {
    int v = (t >= off) ? ts[t - off] : 0;
    __syncthreads();
    ts[t] += v;
    __syncthreads();
  }
  int excl = ts[t] - local + coff[ch];
  int i0 = base + t * 4;
  if (i0 + 0 < n) { cnt[i0 + 0] = excl;                cur[i0 + 0] = excl; }
  if (i0 + 1 < n) { cnt[i0 + 1] = excl + a0;           cur[i0 + 1] = excl + a0; }
  if (i0 + 2 < n) { cnt[i0 + 2] = excl + a0 + a1;      cur[i0 + 2] = excl + a0 + a1; }
  if (i0 + 3 < n) { cnt[i0 + 3] = excl + a0 + a1 + a2; cur[i0 + 3] = excl + a0 + a1 + a2; }
}

// packed scatter: one 8B store per edge
__global__ void csr_scatter2(const int* __restrict__ rowsA, const int* __restrict__ colsA,
                             const float* __restrict__ valsA, int* __restrict__ curA,
                             int2* __restrict__ scvA,
                             const int* __restrict__ rowsB, const int* __restrict__ colsB,
                             const float* __restrict__ valsB, int* __restrict__ curB,
                             int2* __restrict__ scvB) {
  int b = blockIdx.x;
  if (b < GADJE) {
    int e = b * 256 + threadIdx.x;
    if (e >= NNZADJ) return;
    int r = __ldg(rowsA + e);
    int p = atomicAdd(&curA[r], 1);
    scvA[p] = make_int2(__ldg(colsA + e), __float_as_int(__ldg(valsA + e)));
  } else {
    int e = (b - GADJE) * 256 + threadIdx.x;
    if (e >= NNZR) return;
    int r = __ldg(rowsB + e);
    int p = atomicAdd(&curB[r], 1);
    scvB[p] = make_int2(__ldg(colsB + e), __float_as_int(__ldg(valsB + e)));
  }
}

// ================= phase 2 (1D grid): r_fused both mods + gumbel-items + cge1 =================
__global__ void phase2_kernel(const int* __restrict__ startR, const int2* __restrict__ scvR,
                              const float* __restrict__ ihl0, const float* __restrict__ ihl1,
                              const float4* __restrict__ itfc,
                              float* __restrict__ uhl0, float* __restrict__ uhl1,
                              float4* __restrict__ m0c,
                              float* __restrict__ ih0, float* __restrict__ ih1,
                              unsigned ki00, unsigned ki01, unsigned ki10, unsigned ki11,
                              const int* __restrict__ startA, const int2* __restrict__ scvA,
                              const float2* __restrict__ Gu, const float2* __restrict__ Gi,
                              uint32_t* __restrict__ e1h) {
  int bx = blockIdx.x;
  int wid = threadIdx.x >> 5, lane = threadIdx.x & 31;
  if (bx < GUSERB) {
    // fused r-spmm, BOTH modalities: ihl->uhl (both) and itfc->m0c
    int row = bx * 8 + wid;
    if (row >= NUSERS) return;
    int s = startR[row], e = startR[row + 1];
    float a0 = 0.f, a1 = 0.f;
    float4 m = make_float4(0.f, 0.f, 0.f, 0.f);
    for (int i = s; i < e; i++) {
      int2 cv = __ldg(scvR + i);
      int c = cv.x;
      float v = __int_as_float(cv.y);
      float s0 = __ldg(ihl0 + (size_t)c * 32 + lane);
      float s1 = __ldg(ihl1 + (size_t)c * 32 + lane);
      float4 f = __ldg(itfc + (size_t)c * 32 + lane);
      a0 = fmaf(v, s0, a0); a1 = fmaf(v, s1, a1);
      m.x = fmaf(v, f.x, m.x); m.y = fmaf(v, f.y, m.y);
      m.z = fmaf(v, f.z, m.z); m.w = fmaf(v, f.w, m.w);
    }
    uhl0[(size_t)row * 32 + lane] = a0;
    uhl1[(size_t)row * 32 + lane] = a1;
    m0c[(size_t)row * 32 + lane] = m;
  } else if (bx < GUSERB + 2 * GITMB) {
    int sec = bx - GUSERB;
    int mmod = sec >= GITMB;
    int row = (mmod ? sec - GITMB : sec) * 8 + wid;
    if (row >= NITEMS) return;
    gumbel_row(mmod ? ihl1 : ihl0, mmod ? ih1 : ih0, row, lane,
               mmod ? ki10 : ki00, mmod ? ki11 : ki01);
  } else {
    int row = (bx - GUSERB - 2 * GITMB) * 8 + wid;
    if (row >= NNODES) return;
    int s = startA[row], e = startA[row + 1];
    float ax = 0.f, ay = 0.f;
    int i = s;
    for (; i + 1 < e; i += 2) {
      int2 cv0 = __ldg(scvA + i), cv1 = __ldg(scvA + i + 1);
      int c0 = cv0.x, c1 = cv1.x;
      float v0 = __int_as_float(cv0.y), v1 = __int_as_float(cv1.y);
      const float2* x0p = (c0 < NUSERS) ? Gu + (size_t)c0 * 32 : Gi + (size_t)(c0 - NUSERS) * 32;
      const float2* x1p = (c1 < NUSERS) ? Gu + (size_t)c1 * 32 : Gi + (size_t)(c1 - NUSERS) * 32;
      float2 x0 = __ldg(x0p + lane), x1 = __ldg(x1p + lane);
      ax = fmaf(v0, x0.x, ax); ay = fmaf(v0, x0.y, ay);
      ax = fmaf(v1, x1.x, ax); ay = fmaf(v1, x1.y, ay);
    }
    for (; i < e; i++) {
      int2 cv = __ldg(scvA + i);
      int c = cv.x;
      float v = __int_as_float(cv.y);
      const float2* xp = (c < NUSERS) ? Gu + (size_t)c * 32 : Gi + (size_t)(c - NUSERS) * 32;
      float2 xv = __ldg(xp + lane);
      ax = fmaf(v, xv.x, ax); ay = fmaf(v, xv.y, ay);
    }
    e1h[(size_t)row * 32 + lane] = bf16pack(ax, ay);
  }
}

// ================= phase 3: mega adj pass (cge2+combine, mge both) + gumbel-u =================
__global__ void phase3_kernel(const int* __restrict__ startA, const int2* __restrict__ scvA,
                              const uint32_t* __restrict__ e1h,
                              const float2* __restrict__ Gu, const float2* __restrict__ Gi,
                              float2* __restrict__ cge,
                              const float4* __restrict__ m0c,
                              const float4* __restrict__ itfc,
                              const float* __restrict__ inv,
                              float2* __restrict__ m10, float2* __restrict__ m11,
                              const float* __restrict__ uhl0, const float* __restrict__ uhl1,
                              float* __restrict__ uh0, float* __restrict__ uh1,
                              unsigned ku00, unsigned ku01, unsigned ku10, unsigned ku11) {
  int bx = blockIdx.x;
  int wid = threadIdx.x >> 5, lane = threadIdx.x & 31;
  if (bx < GNODEB) {
    int row = bx * 8 + wid;
    if (row >= NNODES) return;
    int s = startA[row], e = startA[row + 1];
    float ex = 0.f, ey = 0.f;
    float vx = 0.f, vy = 0.f;
    float tx = 0.f, ty = 0.f;
    for (int i = s; i < e; i++) {
      int2 cv = __ldg(scvA + i);
      int c = cv.x;
      float v = __int_as_float(cv.y);
      float2 ev = bf16unpack(__ldg(e1h + (size_t)c * 32 + lane));
      float vm = v;
      float4 f;
      if (c < NUSERS) {
        vm = v * __ldg(inv + c);
        f = __ldg(m0c + (size_t)c * 32 + lane);
      } else {
        f = __ldg(itfc + (size_t)(c - NUSERS) * 32 + lane);
      }
      ex = fmaf(v, ev.x, ex); ey = fmaf(v, ev.y, ey);
      vx = fmaf(vm, f.x, vx); vy = fmaf(vm, f.y, vy);
      tx = fmaf(vm, f.z, tx); ty = fmaf(vm, f.w, ty);
    }
    float2 ego = (row < NUSERS) ? __ldg(Gu + (size_t)row * 32 + lane)
                                : __ldg(Gi + (size_t)(row - NUSERS) * 32 + lane);
    float2 e1v = bf16unpack(e1h[(size_t)row * 32 + lane]);
    cge[(size_t)row * 32 + lane] = make_float2((ego.x + e1v.x + ex) * (1.0f / 3.0f),
                                               (ego.y + e1v.y + ey) * (1.0f / 3.0f));
    m10[(size_t)row * 32 + lane] = make_float2(vx, vy);
    m11[(size_t)row * 32 + lane] = make_float2(tx, ty);
  } else if (bx < GNODEB + GUSERB) {
    int row = (bx - GNODEB) * 8 + wid;
    if (row >= NUSERS) return;
    gumbel_row(uhl0, uh0, row, lane, ku00, ku01);
  } else {
    int row = (bx - GNODEB - GUSERB) * 8 + wid;
    if (row >= NUSERS) return;
    gumbel_row(uhl1, uh1, row, lane, ku10, ku11);
  }
}

// ---------------- lat[32,64] += ih^T @ icge, both modalities (lat pre-zeroed) ----------------
__global__ void lat_both_kernel(const float* __restrict__ w0, const float* __restrict__ w1,
                                const float* __restrict__ icge,
                                float* __restrict__ lat0, float* __restrict__ lat1, int chunk) {
  const float* w = blockIdx.y ? w1 : w0;
  float* lat = blockIdx.y ? lat1 : lat0;
  int lane = threadIdx.x & 31;
  int kg = threadIdx.x >> 5;
  int start = blockIdx.x * chunk;
  int end = min(start + chunk, NITEMS);
  float acc[8] = {0, 0, 0, 0, 0, 0, 0, 0};
  for (int it = start; it < end; ++it) {
    float wv = w[it * HH + lane];
    const float* cr = icge + it * EK + kg * 8;
#pragma unroll
    for (int j = 0; j < 8; j++) acc[j] = fmaf(wv, __ldg(cr + j), acc[j]);
  }
#pragma unroll
  for (int j = 0; j < 8; j++) atomicAdd(&lat[lane * EK + kg * 8 + j], acc[j]);
}

// ---------------- fused hyper-apply + final, warp per row ----------------
#define OI   (NUSERS * EK)
#define OHVU ((NUSERS + NITEMS) * EK)
#define OHVI (OHVU + NUSERS * EK)
#define OHTU (OHVI + NITEMS * EK)
#define OHTI (OHTU + NUSERS * EK)
__global__ void final_fused(float* __restrict__ out, const float* __restrict__ cge,
                            const float* __restrict__ m1a, const float* __restrict__ m1b,
                            const float* __restrict__ ih0, const float* __restrict__ ih1,
                            const float* __restrict__ uh0, const float* __restrict__ uh1,
                            const float* __restrict__ lat0, const float* __restrict__ lat1) {
  __shared__ float slA[HH * EK];
  __shared__ float slB[HH * EK];
  for (int t = threadIdx.x; t < HH * EK; t += 256) { slA[t] = lat0[t]; slB[t] = lat1[t]; }
  __syncthreads();
  int row = blockIdx.x * 8 + (threadIdx.x >> 5);
  if (row >= NNODES) return;
  int lane = threadIdx.x & 31;
  const float* w0;
  const float* w1;
  float *outV, *outT, *dst;
  if (row < NUSERS) {
    w0 = uh0 + row * HH; w1 = uh1 + row * HH;
    outV = out + OHVU + row * EK; outT = out + OHTU + row * EK;
    dst = out + row * EK;
  } else {
    int ir = row - NUSERS;
    w0 = ih0 + ir * HH; w1 = ih1 + ir * HH;
    outV = out + OHVI + ir * EK; outT = out + OHTI + ir * EK;
    dst = out + OI + ir * EK;
  }
  float wl0 = w0[lane], wl1 = w1[lane];
  float s0 = 0.f, s1 = 0.f, t0 = 0.f, t1 = 0.f;
#pragma unroll
  for (int h = 0; h < HH; h++) {
    float wv0 = __shfl_sync(0xffffffffu, wl0, h);
    float wv1 = __shfl_sync(0xffffffffu, wl1, h);
    s0 = fmaf(wv0, slA[h * EK + lane], s0);
    s1 = fmaf(wv0, slA[h * EK + lane + 32], s1);
    t0 = fmaf(wv1, slB[h * EK + lane], t0);
    t1 = fmaf(wv1, slB[h * EK + lane + 32], t1);
  }
  outV[lane] = s0; outV[lane + 32] = s1;
  outT[lane] = t0; outT[lane + 32] = t1;
  int b = row * EK;
  float a0 = m1a[b + lane], a1 = m1a[b + lane + 32];
  float c0 = m1b[b + lane], c1 = m1b[b + lane + 32];
  float g0 = s0 + t0, g1 = s1 + t1;
  float sa = a0 * a0 + a1 * a1;
  float sc = c0 * c0 + c1 * c1;
  float sg = g0 * g0 + g1 * g1;
#pragma unroll
  for (int s = 16; s; s >>= 1) {
    sa += __shfl_xor_sync(0xffffffffu, sa, s);
    sc += __shfl_xor_sync(0xffffffffu, sc, s);
    sg += __shfl_xor_sync(0xffffffffu, sg, s);
  }
  float ia = 1.0f / fmaxf(sqrtf(sa), 1e-12f);
  float ic = 1.0f / fmaxf(sqrtf(sc), 1e-12f);
  float ig = 0.2f / fmaxf(sqrtf(sg), 1e-12f);
  dst[lane]      = cge[b + lane]      + a0 * ia + c0 * ic + g0 * ig;
  dst[lane + 32] = cge[b + lane + 32] + a1 * ia + c1 * ic + g1 * ig;
}

// ================================================================================
extern "C" void kernel_launch(void* const* d_in, const int* in_sizes, int n_in,
                              void* d_out, int out_size) {
  const float* Gu       = (const float*)d_in[0];
  const float* Gi       = (const float*)d_in[1];
  const float* feat_v   = (const float*)d_in[2];
  const float* feat_t   = (const float*)d_in[3];
  const float* trs_v    = (const float*)d_in[4];
  const float* trs_t    = (const float*)d_in[5];
  const float* hyp_v    = (const float*)d_in[6];
  const float* hyp_t    = (const float*)d_in[7];
  const float* inv      = (const float*)d_in[8];
  const float* adj_vals = (const float*)d_in[9];
  const float* r_vals   = (const float*)d_in[10];
  const int*   adj_rows = (const int*)d_in[11];
  const int*   adj_cols = (const int*)d_in[12];
  const int*   r_rows   = (const int*)d_in[13];
  const int*   r_cols   = (const int*)d_in[14];
  float* out = (float*)d_out;
  int Fv = in_sizes[2] / NITEMS;
  int Ft = in_sizes[3] / NITEMS;

  float *p_ihl, *p_uhl, *p_ih, *p_uh, *p_e0, *p_m1, *p_lat;
  float4* p_itfc;
  float4* p_m0c;
  uint32_t* p_e1h;
  int *p_hist, *pA_cur, *pA_csum, *pA_coff, *pR_cur, *pR_csum, *pR_coff;
  int2 *pA_scv, *pR_scv;
  cudaGetSymbolAddress((void**)&p_itfc, g_itfc);
  cudaGetSymbolAddress((void**)&p_ihl, g_ihl);
  cudaGetSymbolAddress((void**)&p_uhl, g_uhl);
  cudaGetSymbolAddress((void**)&p_ih,  g_ih);
  cudaGetSymbolAddress((void**)&p_uh,  g_uh);
  cudaGetSymbolAddress((void**)&p_e0,  g_e0);
  cudaGetSymbolAddress((void**)&p_e1h, g_e1h);
  cudaGetSymbolAddress((void**)&p_m0c, g_m0c);
  cudaGetSymbolAddress((void**)&p_m1,  g_m1);
  cudaGetSymbolAddress((void**)&p_lat, g_lat);
  cudaGetSymbolAddress((void**)&p_hist, g_hist);
  cudaGetSymbolAddress((void**)&pA_cur,  g_curA);
  cudaGetSymbolAddress((void**)&pA_scv,  g_scvA);
  cudaGetSymbolAddress((void**)&pA_csum, g_csumA);
  cudaGetSymbolAddress((void**)&pA_coff, g_coffA);
  cudaGetSymbolAddress((void**)&pR_cur,  g_curR);
  cudaGetSymbolAddress((void**)&pR_scv,  g_scvR);
  cudaGetSymbolAddress((void**)&pR_csum, g_csumR);
  cudaGetSymbolAddress((void**)&pR_coff, g_coffR);
  int* pA_start = p_hist;
  int* pR_start = p_hist + NNODES + 1;
  float* p_ihlT = p_ihl + NITEMS * HH;
  float* p_uhlT = p_uhl + NUSERS * HH;
  float* p_ihT  = p_ih + NITEMS * HH;
  float* p_uhT  = p_uh + NUSERS * HH;
  float* p_m1T  = p_m1 + NNODES * EK;
  float* p_latT = p_lat + HH * EK;

  // JAX threefry keys
  uint32_t ki0[2], ki1[2], ku0[2], ku1[2];
  for (int m = 0; m < 2; m++) {
    uint32_t km0, km1;
    tf2x32(0u, 42u, 0u, (uint32_t)m, &km0, &km1);
    tf2x32(km0, km1, 0u, 0u, &ki0[m], &ki1[m]);
    tf2x32(km0, km1, 0u, 1u, &ku0[m], &ku1[m]);
  }

  // ---- zero CSR histograms (one memset) + lat ----
  cudaMemsetAsync(p_hist, 0, HIST_TOTAL * sizeof(int), 0);
  cudaMemsetAsync(p_lat, 0, 2 * HH * EK * sizeof(float), 0);

  // ---- GEMMs + CSR histograms in one launch ----
  gemm_hist_kernel<<<dim3(GEMMB + GADJE, 2), 256>>>(
      feat_v, feat_t, trs_v, trs_t, hyp_v, hyp_t,
      (float2*)p_itfc, p_ihl, p_ihlT, Fv, Ft,
      adj_rows, r_rows, pA_start, pR_start);

  // ---- CSR scans (3 parallel launches) + packed scatter ----
  csr_chunksum2<<<NCHA + NCHR, 256>>>(pA_start, pR_start, pA_csum, pR_csum, NNODES, NUSERS);
  csr_scanchunks2<<<2, 32>>>(pA_csum, pA_coff, pA_start, pR_csum, pR_coff, pR_start);
  csr_chunkscan2<<<NCHA + NCHR, 256>>>(pA_start, pA_coff, pA_cur,
                                       pR_start, pR_coff, pR_cur, NNODES, NUSERS);
  csr_scatter2<<<GADJE + GRE, 256>>>(adj_rows, adj_cols, adj_vals, pA_cur, pA_scv,
                                     r_rows, r_cols, r_vals, pR_cur, pR_scv);

  // ---- phase 2: r_fused(both) + gumbel-items + cge1 ----
  phase2_kernel<<<GUSERB + 2 * GITMB + GNODEB, 256>>>(
      pR_start, pR_scv, p_ihl, p_ihlT, p_itfc,
      p_uhl, p_uhlT, p_m0c,
      p_ih, p_ihT, ki0[0], ki1[0], ki0[1], ki1[1],
      pA_start, pA_scv, (const float2*)Gu, (const float2*)Gi, p_e1h);

  // ---- phase 3: mega adj (cge2 + mge both) + gumbel-u ----
  phase3_kernel<<<GNODEB + 2 * GUSERB, 256>>>(
      pA_start, pA_scv, p_e1h,
      (const float2*)Gu, (const float2*)Gi, (float2*)p_e0,
      p_m0c, p_itfc, inv,
      (float2*)p_m1, (float2*)p_m1T,
      p_uhl, p_uhlT, p_uh, p_uhT, ku0[0], ku1[0], ku0[1], ku1[1]);

  // ---- hyper path + final ----
  lat_both_kernel<<<dim3(120, 2), 256>>>(p_ih, p_ihT, p_e0 + NUSERS * EK, p_lat, p_latT, 250);
  final_fused<<<GNODEB, 256>>>(out, p_e0, p_m1, p_m1T,
                               p_ih, p_ihT, p_uh, p_uhT, p_lat, p_latT);
}

// round 17
// speedup vs baseline: 1.0980x; 1.0214x over previous
#include <cuda_runtime.h>
#include <stdint.h>

#define NUSERS 50000
#define NITEMS 30000
#define NNODES 80000
#define EK 64
#define HH 32
#define NNZADJ 2000000
#define NNZR 1000000
#define NCHA ((NNODES + 1023) / 1024)
#define NCHR ((NUSERS + 1023) / 1024)
#define GEMMB 235                       // (NITEMS+127)/128
#define GADJE ((NNZADJ + 255) / 256)    // 7813
#define GRE   ((NNZR + 255) / 256)      // 3907
#define GCONV (GADJE - GRE)             // 3906 spare y=1 blocks for ego convert
#define GUSERB ((NUSERS + 7) / 8)       // 6250
#define GITMB  ((NITEMS + 7) / 8)       // 3750
#define GNODEB ((NNODES + 7) / 8)       // 10000

// ---------------- scratch (device globals; allocation is forbidden) ----------------
__device__ float4 g_itfc[NITEMS * 32];       // item feats, interleaved fp32 {mod0.xy, mod1.xy}
__device__ float g_ihl[2][NITEMS * HH];      // hyper logits (fp32; feeds gumbel)
__device__ float g_uhl[2][NUSERS * HH];
__device__ float g_ih[2][NITEMS * HH];
__device__ float g_uh[2][NUSERS * HH];
__device__ float g_e0[NNODES * EK];          // cge (fp32)
__device__ uint32_t g_egoh[NNODES * 32];     // concat(Gu,Gi) as bf16x2 (cge1 gather only)
__device__ uint32_t g_e1h[NNODES * 32];      // e1 as bf16x2 per lane-pair (damped path: safe)
__device__ float4 g_m0c[NUSERS * 32];        // m0 interleaved fp32, PRE-SCALED by inv[row]
__device__ float g_m1[2][NNODES * EK];
__device__ float g_lat[2][HH * EK];
// CSR scratch: histA and histR in ONE buffer (single memset)
#define HIST_TOTAL (NNODES + 1 + NUSERS + 1)
__device__ int   g_hist[HIST_TOTAL];
__device__ int   g_curA[NNODES];
__device__ int2  g_scvA[NNZADJ];             // packed {col, val-bits}
__device__ int   g_csumA[NCHA];
__device__ int   g_coffA[NCHA];
__device__ int   g_curR[NUSERS];
__device__ int2  g_scvR[NNZR];
__device__ int   g_csumR[NCHR];
__device__ int   g_coffR[NCHR];

// ---------------- threefry2x32 (JAX-compatible, 20 rounds) ----------------
__host__ __device__ __forceinline__ void tf2x32(uint32_t k0, uint32_t k1,
                                                uint32_t x0, uint32_t x1,
                                                uint32_t* o0, uint32_t* o1) {
  uint32_t ks2 = k0 ^ k1 ^ 0x1BD11BDAu;
  uint32_t v0 = x0 + k0, v1 = x1 + k1;
#define TFR(r) { v0 += v1; v1 = (v1 << (r)) | (v1 >> (32 - (r))); v1 ^= v0; }
  TFR(13) TFR(15) TFR(26) TFR(6)
  v0 += k1;  v1 += ks2 + 1u;
  TFR(17) TFR(29) TFR(16) TFR(24)
  v0 += ks2; v1 += k0 + 2u;
  TFR(13) TFR(15) TFR(26) TFR(6)
  v0 += k0;  v1 += k1 + 3u;
  TFR(17) TFR(29) TFR(16) TFR(24)
  v0 += k1;  v1 += ks2 + 4u;
  TFR(13) TFR(15) TFR(26) TFR(6)
  v0 += ks2; v1 += k0 + 5u;
#undef TFR
  *o0 = v0; *o1 = v1;
}

// ---------------- bf16 pack/unpack + mma helpers ----------------
__device__ __forceinline__ uint2 bf16split2(float x0, float x1) {
  uint32_t h;
  asm("cvt.rn.bf16x2.f32 %0, %1, %2;" : "=r"(h) : "f"(x1), "f"(x0));
  float h0 = __uint_as_float(h << 16);
  float h1 = __uint_as_float(h & 0xFFFF0000u);
  uint32_t l;
  asm("cvt.rn.bf16x2.f32 %0, %1, %2;" : "=r"(l) : "f"(x1 - h1), "f"(x0 - h0));
  return make_uint2(h, l);
}
__device__ __forceinline__ uint32_t bf16pack(float x0, float x1) {
  uint32_t h;
  asm("cvt.rn.bf16x2.f32 %0, %1, %2;" : "=r"(h) : "f"(x1), "f"(x0));
  return h;
}
__device__ __forceinline__ float2 bf16unpack(uint32_t u) {
  return make_float2(__uint_as_float(u << 16), __uint_as_float(u & 0xFFFF0000u));
}

__device__ __forceinline__ void mma16(float* c, const uint32_t* a, const uint32_t* b) {
  asm volatile("mma.sync.aligned.m16n8k16.row.col.f32.bf16.bf16.f32 "
               "{%0,%1,%2,%3}, {%4,%5,%6,%7}, {%8,%9}, {%0,%1,%2,%3};"
               : "+f"(c[0]), "+f"(c[1]), "+f"(c[2]), "+f"(c[3])
               : "r"(a[0]), "r"(a[1]), "r"(a[2]), "r"(a[3]), "r"(b[0]), "r"(b[1]));
}

// ---------------- gumbel softmax row helper ----------------
__device__ __forceinline__ void gumbel_row(const float* __restrict__ logits,
                                           float* __restrict__ out,
                                           int row, int lane, unsigned k0, unsigned k1) {
  unsigned idx = (unsigned)row * 32u + (unsigned)lane;
  unsigned b0, b1;
  tf2x32(k0, k1, 0u, idx, &b0, &b1);
  unsigned bits = b0 ^ b1;
  float f = __uint_as_float((bits >> 9) | 0x3f800000u) - 1.0f;
  const float TINY = 1.1754943508222875e-38f;
  float u = fmaxf(TINY, f + TINY);
  float g = -logf(-logf(u));
  float z = (logits[row * 32 + lane] + g) * 5.0f;
  float mx = z;
#pragma unroll
  for (int s = 16; s; s >>= 1) mx = fmaxf(mx, __shfl_xor_sync(0xffffffffu, mx, s));
  float e = expf(z - mx);
  float sm = e;
#pragma unroll
  for (int s = 16; s; s >>= 1) sm += __shfl_xor_sync(0xffffffffu, sm, s);
  out[row * 32 + lane] = e / sm;
}

// ================= fused GEMM(bf16x3) + CSR histogram + ego convert, one launch =================
#define ASP 132
#define BSP 100
__global__ __launch_bounds__(256, 2)
void gemm_hist_kernel(const float* __restrict__ A0, const float* __restrict__ A1,
                      const float* __restrict__ Bt0, const float* __restrict__ Bt1,
                      const float* __restrict__ Bh0, const float* __restrict__ Bh1,
                      float2* __restrict__ itfc2,
                      float* __restrict__ Cl0, float* __restrict__ Cl1,
                      int F0, int F1,
                      const int* __restrict__ rowsA, const int* __restrict__ rowsR,
                      int* __restrict__ cntA, int* __restrict__ cntR,
                      const float* __restrict__ Gu, const float* __restrict__ Gi,
                      uint32_t* __restrict__ egoh) {
  if (blockIdx.x >= GEMMB) {
    int hb = blockIdx.x - GEMMB;
    if (blockIdx.y == 0) {
      int e = hb * 256 + threadIdx.x;
      if (e < NNZADJ) atomicAdd(&cntA[__ldg(rowsA + e)], 1);
    } else {
      if (hb < GRE) {
        int e = hb * 256 + threadIdx.x;
        if (e < NNZR) atomicAdd(&cntR[__ldg(rowsR + e)], 1);
      } else {
        // spare blocks: convert concat(Gu,Gi) -> bf16x2 egoh
        int t = (hb - GRE) * 256 + threadIdx.x;
        for (int i = t; i < NNODES * 32; i += GCONV * 256) {
          int node = i >> 5, p = i & 31;
          const float* src = (node < NUSERS) ? Gu + (size_t)node * 64 + 2 * p
                                             : Gi + (size_t)(node - NUSERS) * 64 + 2 * p;
          egoh[i] = bf16pack(__ldg(src), __ldg(src + 1));
        }
      }
    }
    return;
  }
  __shared__ uint2 AsP[16][ASP];
  __shared__ uint2 BsP[16][BSP];
  const int mmod = blockIdx.y;
  const float* A  = mmod ? A1 : A0;
  const float* Bt = mmod ? Bt1 : Bt0;
  const float* Bh = mmod ? Bh1 : Bh0;
  float* Cl = mmod ? Cl1 : Cl0;
  const int F = mmod ? F1 : F0;

  const int row0 = blockIdx.x * 128;
  const int tid = threadIdx.x;
  const int wid = tid >> 5, lane = tid & 31;
  const int wr = wid >> 1, wc = wid & 1;
  const int qid = lane >> 2, qtid = lane & 3;

  const int lr = tid >> 1;
  const int lk2 = (tid & 1) * 8;
  const int gr_l = row0 + lr;
  const bool rok = gr_l < NITEMS;
  const float* Arow = A + (size_t)gr_l * F + lk2 * 2;

  float4 a4[4];
  float bb0[6], bb1[6];
  const float4 z4 = make_float4(0.f, 0.f, 0.f, 0.f);
#pragma unroll
  for (int i = 0; i < 4; i++) a4[i] = rok ? __ldg((const float4*)(Arow + 4 * i)) : z4;
#pragma unroll
  for (int i = 0; i < 6; i++) {
    int p = tid + 256 * i, k2 = p / 96, c = p - k2 * 96;
    int kk = 2 * k2;
    if (c < 64) { bb0[i] = __ldg(Bt + kk * 64 + c); bb1[i] = __ldg(Bt + (kk + 1) * 64 + c); }
    else        { bb0[i] = __ldg(Bh + kk * 32 + c - 64); bb1[i] = __ldg(Bh + (kk + 1) * 32 + c - 64); }
  }

  float acc[2][6][4];
#pragma unroll
  for (int mt = 0; mt < 2; mt++)
#pragma unroll
    for (int nt = 0; nt < 6; nt++)
#pragma unroll
      for (int j = 0; j < 4; j++) acc[mt][nt][j] = 0.0f;

  for (int k0 = 0; k0 < F; k0 += 32) {
    float av[16];
#pragma unroll
    for (int i = 0; i < 4; i++) {
      av[4 * i + 0] = a4[i].x; av[4 * i + 1] = a4[i].y;
      av[4 * i + 2] = a4[i].z; av[4 * i + 3] = a4[i].w;
    }
#pragma unroll
    for (int j = 0; j < 8; j++)
      AsP[lk2 + j][lr] = bf16split2(av[2 * j], av[2 * j + 1]);
#pragma unroll
    for (int i = 0; i < 6; i++) {
      int p = tid + 256 * i, k2 = p / 96, c = p - k2 * 96;
      BsP[k2][c] = bf16split2(bb0[i], bb1[i]);
    }
    __syncthreads();
    int kn = k0 + 32;
    if (kn < F) {
#pragma unroll
      for (int i = 0; i < 4; i++) a4[i] = rok ? __ldg((const float4*)(Arow + kn + 4 * i)) : z4;
#pragma unroll
      for (int i = 0; i < 6; i++) {
        int p = tid + 256 * i, k2 = p / 96, c = p - k2 * 96;
        int kk = kn + 2 * k2;
        if (c < 64) { bb0[i] = __ldg(Bt + kk * 64 + c); bb1[i] = __ldg(Bt + (kk + 1) * 64 + c); }
        else        { bb0[i] = __ldg(Bh + kk * 32 + c - 64); bb1[i] = __ldg(Bh + (kk + 1) * 32 + c - 64); }
      }
    }
#pragma unroll
    for (int ks = 0; ks < 2; ks++) {
      const int kb = ks * 8;
      uint2 a2[2][4];
#pragma unroll
      for (int mt = 0; mt < 2; mt++) {
        int ar = wr * 32 + mt * 16 + qid;
        a2[mt][0] = AsP[kb + qtid][ar];
        a2[mt][1] = AsP[kb + qtid][ar + 8];
        a2[mt][2] = AsP[kb + qtid + 4][ar];
        a2[mt][3] = AsP[kb + qtid + 4][ar + 8];
      }
#pragma unroll
      for (int nt = 0; nt < 6; nt++) {
        int bn = wc * 48 + nt * 8 + qid;
        uint2 b0 = BsP[kb + qtid][bn];
        uint2 b1 = BsP[kb + qtid + 4][bn];
        uint32_t bhv[2] = {b0.x, b1.x};
        uint32_t blv[2] = {b0.y, b1.y};
#pragma unroll
        for (int mt = 0; mt < 2; mt++) {
          uint32_t ah[4] = {a2[mt][0].x, a2[mt][1].x, a2[mt][2].x, a2[mt][3].x};
          uint32_t al[4] = {a2[mt][0].y, a2[mt][1].y, a2[mt][2].y, a2[mt][3].y};
          mma16(acc[mt][nt], ah, bhv);
          mma16(acc[mt][nt], ah, blv);
          mma16(acc[mt][nt], al, bhv);
        }
      }
    }
    __syncthreads();
  }

#pragma unroll
  for (int mt = 0; mt < 2; mt++) {
    int gr = row0 + wr * 32 + mt * 16 + qid;
#pragma unroll
    for (int nt = 0; nt < 6; nt++) {
      int cc = wc * 48 + nt * 8 + 2 * qtid;
      if (gr < NITEMS) {
        if (cc < 64) itfc2[((size_t)gr * 32 + (cc >> 1)) * 2 + mmod] = make_float2(acc[mt][nt][0], acc[mt][nt][1]);
        else         { Cl[gr * 32 + cc - 64] = acc[mt][nt][0]; Cl[gr * 32 + cc - 63] = acc[mt][nt][1]; }
      }
      if (gr + 8 < NITEMS) {
        if (cc < 64) itfc2[((size_t)(gr + 8) * 32 + (cc >> 1)) * 2 + mmod] = make_float2(acc[mt][nt][2], acc[mt][nt][3]);
        else         { Cl[(gr + 8) * 32 + cc - 64] = acc[mt][nt][2]; Cl[(gr + 8) * 32 + cc - 63] = acc[mt][nt][3]; }
      }
    }
  }
}

// ================= CSR scans (3 parallel launches) =================
__global__ void csr_chunksum2(const int* __restrict__ cntA, const int* __restrict__ cntB,
                              int* __restrict__ csumA, int* __restrict__ csumB,
                              int nA, int nB) {
  __shared__ int ts[256];
  const int* cnt;
  int* csum;
  int n, ch;
  if (blockIdx.x < NCHA) { cnt = cntA; csum = csumA; n = nA; ch = blockIdx.x; }
  else                   { cnt = cntB; csum = csumB; n = nB; ch = blockIdx.x - NCHA; }
  int base = ch * 1024;
  int s = 0;
  for (int i = threadIdx.x; i < 1024; i += 256) {
    int idx = base + i;
    s += (idx < n) ? cnt[idx] : 0;
  }
  ts[threadIdx.x] = s;
  __syncthreads();
  for (int off = 128; off; off >>= 1) {
    if (threadIdx.x < off) ts[threadIdx.x] += ts[threadIdx.x + off];
    __syncthreads();
  }
  if (threadIdx.x == 0) csum[ch] = ts[0];
}

__global__ void csr_scanchunks2(const int* __restrict__ csumA, int* __restrict__ coffA,
                                int* __restrict__ startA,
                                const int* __restrict__ csumB, int* __restrict__ coffB,
                                int* __restrict__ startB) {
  if (threadIdx.x != 0) return;
  if (blockIdx.x == 0) {
    int run = 0;
    for (int i = 0; i < NCHA; i++) { coffA[i] = run; run += csumA[i]; }
    startA[NNODES] = NNZADJ;
  } else {
    int run = 0;
    for (int i = 0; i < NCHR; i++) { coffB[i] = run; run += csumB[i]; }
    startB[NUSERS] = NNZR;
  }
}

__global__ void csr_chunkscan2(int* __restrict__ cntA, const int* __restrict__ coffA,
                               int* __restrict__ curA,
                               int* __restrict__ cntB, const int* __restrict__ coffB,
                               int* __restrict__ curB, int nA, int nB) {
  __shared__ int sm[1024];
  __shared__ int ts[256];
  int* cnt;
  const int* coff;
  int* cur;
  int n, ch;
  if (blockIdx.x < NCHA) { cnt = cntA; coff = coffA; cur = curA; n = nA; ch = blockIdx.x; }
  else                   { cnt = cntB; coff = coffB; cur = curB; n = nB; ch = blockIdx.x - NCHA; }
  int base = ch * 1024;
  for (int i = threadIdx.x; i < 1024; i += 256)
    sm[i] = (base + i < n) ? cnt[base + i] : 0;
  __syncthreads();
  int t = threadIdx.x;
  int a0 = sm[t * 4], a1 = sm[t * 4 + 1], a2 = sm[t * 4 + 2], a3 = sm[t * 4 + 3];
  int local = a0 + a1 + a2 + a3;
  ts[t] = local;
  __syncthreads();
  for (int off = 1; off < 256; off <<= 1) {
    int v = (t >= off) ? ts[t - off] : 0;
    __syncthreads();
    ts[t] += v;
    __syncthreads();
  }
  int excl = ts[t] - local + coff[ch];
  int i0 = base + t * 4;
  if (i0 + 0 < n) { cnt[i0 + 0] = excl;                cur[i0 + 0] = excl; }
  if (i0 + 1 < n) { cnt[i0 + 1] = excl + a0;           cur[i0 + 1] = excl + a0; }
  if (i0 + 2 < n) { cnt[i0 + 2] = excl + a0 + a1;      cur[i0 + 2] = excl + a0 + a1; }
  if (i0 + 3 < n) { cnt[i0 + 3] = excl + a0 + a1 + a2; cur[i0 + 3] = excl + a0 + a1 + a2; }
}

// packed scatter: one 8B store per edge
__global__ void csr_scatter2(const int* __restrict__ rowsA, const int* __restrict__ colsA,
                             const float* __restrict__ valsA, int* __restrict__ curA,
                             int2* __restrict__ scvA,
                             const int* __restrict__ rowsB, const int* __restrict__ colsB,
                             const float* __restrict__ valsB, int* __restrict__ curB,
                             int2* __restrict__ scvB) {
  int b = blockIdx.x;
  if (b < GADJE) {
    int e = b * 256 + threadIdx.x;
    if (e >= NNZADJ) return;
    int r = __ldg(rowsA + e);
    int p = atomicAdd(&curA[r], 1);
    scvA[p] = make_int2(__ldg(colsA + e), __float_as_int(__ldg(valsA + e)));
  } else {
    int e = (b - GADJE) * 256 + threadIdx.x;
    if (e >= NNZR) return;
    int r = __ldg(rowsB + e);
    int p = atomicAdd(&curB[r], 1);
    scvB[p] = make_int2(__ldg(colsB + e), __float_as_int(__ldg(valsB + e)));
  }
}

// ================= phase 2 (1D grid): r_fused both mods + gumbel-items + cge1 =================
__global__ void phase2_kernel(const int* __restrict__ startR, const int2* __restrict__ scvR,
                              const float* __restrict__ ihl0, const float* __restrict__ ihl1,
                              const float4* __restrict__ itfc,
                              const float* __restrict__ inv,
                              float* __restrict__ uhl0, float* __restrict__ uhl1,
                              float4* __restrict__ m0c,
                              float* __restrict__ ih0, float* __restrict__ ih1,
                              unsigned ki00, unsigned ki01, unsigned ki10, unsigned ki11,
                              const int* __restrict__ startA, const int2* __restrict__ scvA,
                              const uint32_t* __restrict__ egoh,
                              uint32_t* __restrict__ e1h) {
  int bx = blockIdx.x;
  int wid = threadIdx.x >> 5, lane = threadIdx.x & 31;
  if (bx < GUSERB) {
    // fused r-spmm, BOTH modalities; m0c stored pre-scaled by inv[row]
    int row = bx * 8 + wid;
    if (row >= NUSERS) return;
    int s = startR[row], e = startR[row + 1];
    float a0 = 0.f, a1 = 0.f;
    float4 m = make_float4(0.f, 0.f, 0.f, 0.f);
    for (int i = s; i < e; i++) {
      int2 cv = __ldg(scvR + i);
      int c = cv.x;
      float v = __int_as_float(cv.y);
      float s0 = __ldg(ihl0 + (size_t)c * 32 + lane);
      float s1 = __ldg(ihl1 + (size_t)c * 32 + lane);
      float4 f = __ldg(itfc + (size_t)c * 32 + lane);
      a0 = fmaf(v, s0, a0); a1 = fmaf(v, s1, a1);
      m.x = fmaf(v, f.x, m.x); m.y = fmaf(v, f.y, m.y);
      m.z = fmaf(v, f.z, m.z); m.w = fmaf(v, f.w, m.w);
    }
    uhl0[(size_t)row * 32 + lane] = a0;
    uhl1[(size_t)row * 32 + lane] = a1;
    float iv = __ldg(inv + row);
    m0c[(size_t)row * 32 + lane] = make_float4(m.x * iv, m.y * iv, m.z * iv, m.w * iv);
  } else if (bx < GUSERB + 2 * GITMB) {
    int sec = bx - GUSERB;
    int mmod = sec >= GITMB;
    int row = (mmod ? sec - GITMB : sec) * 8 + wid;
    if (row >= NITEMS) return;
    gumbel_row(mmod ? ihl1 : ihl0, mmod ? ih1 : ih0, row, lane,
               mmod ? ki10 : ki00, mmod ? ki11 : ki01);
  } else {
    int row = (bx - GUSERB - 2 * GITMB) * 8 + wid;
    if (row >= NNODES) return;
    int s = startA[row], e = startA[row + 1];
    float ax = 0.f, ay = 0.f;
    int i = s;
    for (; i + 1 < e; i += 2) {
      int2 cv0 = __ldg(scvA + i), cv1 = __ldg(scvA + i + 1);
      float v0 = __int_as_float(cv0.y), v1 = __int_as_float(cv1.y);
      float2 x0 = bf16unpack(__ldg(egoh + (size_t)cv0.x * 32 + lane));
      float2 x1 = bf16unpack(__ldg(egoh + (size_t)cv1.x * 32 + lane));
      ax = fmaf(v0, x0.x, ax); ay = fmaf(v0, x0.y, ay);
      ax = fmaf(v1, x1.x, ax); ay = fmaf(v1, x1.y, ay);
    }
    for (; i < e; i++) {
      int2 cv = __ldg(scvA + i);
      float v = __int_as_float(cv.y);
      float2 xv = bf16unpack(__ldg(egoh + (size_t)cv.x * 32 + lane));
      ax = fmaf(v, xv.x, ax); ay = fmaf(v, xv.y, ay);
    }
    e1h[(size_t)row * 32 + lane] = bf16pack(ax, ay);
  }
}

// ================= phase 3: mega adj pass (cge2+combine, mge both) + gumbel-u =================
__global__ void phase3_kernel(const int* __restrict__ startA, const int2* __restrict__ scvA,
                              const uint32_t* __restrict__ e1h,
                              const float2* __restrict__ Gu, const float2* __restrict__ Gi,
                              float2* __restrict__ cge,
                              const float4* __restrict__ m0c,
                              const float4* __restrict__ itfc,
                              float2* __restrict__ m10, float2* __restrict__ m11,
                              const float* __restrict__ uhl0, const float* __restrict__ uhl1,
                              float* __restrict__ uh0, float* __restrict__ uh1,
                              unsigned ku00, unsigned ku01, unsigned ku10, unsigned ku11) {
  int bx = blockIdx.x;
  int wid = threadIdx.x >> 5, lane = threadIdx.x & 31;
  if (bx < GNODEB) {
    int row = bx * 8 + wid;
    if (row >= NNODES) return;
    int s = startA[row], e = startA[row + 1];
    float ex = 0.f, ey = 0.f;
    float vx = 0.f, vy = 0.f;
    float tx = 0.f, ty = 0.f;
    for (int i = s; i < e; i++) {
      int2 cv = __ldg(scvA + i);
      int c = cv.x;
      float v = __int_as_float(cv.y);
      float2 ev = bf16unpack(__ldg(e1h + (size_t)c * 32 + lane));
      float4 f = (c < NUSERS) ? __ldg(m0c + (size_t)c * 32 + lane)
                              : __ldg(itfc + (size_t)(c - NUSERS) * 32 + lane);
      ex = fmaf(v, ev.x, ex); ey = fmaf(v, ev.y, ey);
      vx = fmaf(v, f.x, vx); vy = fmaf(v, f.y, vy);
      tx = fmaf(v, f.z, tx); ty = fmaf(v, f.w, ty);
    }
    float2 ego = (row < NUSERS) ? __ldg(Gu + (size_t)row * 32 + lane)
                                : __ldg(Gi + (size_t)(row - NUSERS) * 32 + lane);
    float2 e1v = bf16unpack(e1h[(size_t)row * 32 + lane]);
    cge[(size_t)row * 32 + lane] = make_float2((ego.x + e1v.x + ex) * (1.0f / 3.0f),
                                               (ego.y + e1v.y + ey) * (1.0f / 3.0f));
    m10[(size_t)row * 32 + lane] = make_float2(vx, vy);
    m11[(size_t)row * 32 + lane] = make_float2(tx, ty);
  } else if (bx < GNODEB + GUSERB) {
    int row = (bx - GNODEB) * 8 + wid;
    if (row >= NUSERS) return;
    gumbel_row(uhl0, uh0, row, lane, ku00, ku01);
  } else {
    int row = (bx - GNODEB - GUSERB) * 8 + wid;
    if (row >= NUSERS) return;
    gumbel_row(uhl1, uh1, row, lane, ku10, ku11);
  }
}

// ---------------- lat[32,64] += ih^T @ icge, both modalities (lat pre-zeroed) ----------------
__global__ void lat_both_kernel(const float* __restrict__ w0, const float* __restrict__ w1,
                                const float* __restrict__ icge,
                                float* __restrict__ lat0, float* __restrict__ lat1, int chunk) {
  const float* w = blockIdx.y ? w1 : w0;
  float* lat = blockIdx.y ? lat1 : lat0;
  int lane = threadIdx.x & 31;
  int kg = threadIdx.x >> 5;
  int start = blockIdx.x * chunk;
  int end = min(start + chunk, NITEMS);
  float acc[8] = {0, 0, 0, 0, 0, 0, 0, 0};
  for (int it = start; it < end; ++it) {
    float wv = w[it * HH + lane];
    const float* cr = icge + it * EK + kg * 8;
#pragma unroll
    for (int j = 0; j < 8; j++) acc[j] = fmaf(wv, __ldg(cr + j), acc[j]);
  }
#pragma unroll
  for (int j = 0; j < 8; j++) atomicAdd(&lat[lane * EK + kg * 8 + j], acc[j]);
}

// ---------------- fused hyper-apply + final, warp per row ----------------
#define OI   (NUSERS * EK)
#define OHVU ((NUSERS + NITEMS) * EK)
#define OHVI (OHVU + NUSERS * EK)
#define OHTU (OHVI + NITEMS * EK)
#define OHTI (OHTU + NUSERS * EK)
__global__ void final_fused(float* __restrict__ out, const float* __restrict__ cge,
                            const float* __restrict__ m1a, const float* __restrict__ m1b,
                            const float* __restrict__ ih0, const float* __restrict__ ih1,
                            const float* __restrict__ uh0, const float* __restrict__ uh1,
                            const float* __restrict__ lat0, const float* __restrict__ lat1) {
  __shared__ float slA[HH * EK];
  __shared__ float slB[HH * EK];
  for (int t = threadIdx.x; t < HH * EK; t += 256) { slA[t] = lat0[t]; slB[t] = lat1[t]; }
  __syncthreads();
  int row = blockIdx.x * 8 + (threadIdx.x >> 5);
  if (row >= NNODES) return;
  int lane = threadIdx.x & 31;
  const float* w0;
  const float* w1;
  float *outV, *outT, *dst;
  if (row < NUSERS) {
    w0 = uh0 + row * HH; w1 = uh1 + row * HH;
    outV = out + OHVU + row * EK; outT = out + OHTU + row * EK;
    dst = out + row * EK;
  } else {
    int ir = row - NUSERS;
    w0 = ih0 + ir * HH; w1 = ih1 + ir * HH;
    outV = out + OHVI + ir * EK; outT = out + OHTI + ir * EK;
    dst = out + OI + ir * EK;
  }
  float wl0 = w0[lane], wl1 = w1[lane];
  float s0 = 0.f, s1 = 0.f, t0 = 0.f, t1 = 0.f;
#pragma unroll
  for (int h = 0; h < HH; h++) {
    float wv0 = __shfl_sync(0xffffffffu, wl0, h);
    float wv1 = __shfl_sync(0xffffffffu, wl1, h);
    s0 = fmaf(wv0, slA[h * EK + lane], s0);
    s1 = fmaf(wv0, slA[h * EK + lane + 32], s1);
    t0 = fmaf(wv1, slB[h * EK + lane], t0);
    t1 = fmaf(wv1, slB[h * EK + lane + 32], t1);
  }
  outV[lane] = s0; outV[lane + 32] = s1;
  outT[lane] = t0; outT[lane + 32] = t1;
  int b = row * EK;
  float a0 = m1a[b + lane], a1 = m1a[b + lane + 32];
  float c0 = m1b[b + lane], c1 = m1b[b + lane + 32];
  float g0 = s0 + t0, g1 = s1 + t1;
  float sa = a0 * a0 + a1 * a1;
  float sc = c0 * c0 + c1 * c1;
  float sg = g0 * g0 + g1 * g1;
#pragma unroll
  for (int s = 16; s; s >>= 1) {
    sa += __shfl_xor_sync(0xffffffffu, sa, s);
    sc += __shfl_xor_sync(0xffffffffu, sc, s);
    sg += __shfl_xor_sync(0xffffffffu, sg, s);
  }
  float ia = 1.0f / fmaxf(sqrtf(sa), 1e-12f);
  float ic = 1.0f / fmaxf(sqrtf(sc), 1e-12f);
  float ig = 0.2f / fmaxf(sqrtf(sg), 1e-12f);
  dst[lane]      = cge[b + lane]      + a0 * ia + c0 * ic + g0 * ig;
  dst[lane + 32] = cge[b + lane + 32] + a1 * ia + c1 * ic + g1 * ig;
}

// ================================================================================
extern "C" void kernel_launch(void* const* d_in, const int* in_sizes, int n_in,
                              void* d_out, int out_size) {
  const float* Gu       = (const float*)d_in[0];
  const float* Gi       = (const float*)d_in[1];
  const float* feat_v   = (const float*)d_in[2];
  const float* feat_t   = (const float*)d_in[3];
  const float* trs_v    = (const float*)d_in[4];
  const float* trs_t    = (const float*)d_in[5];
  const float* hyp_v    = (const float*)d_in[6];
  const float* hyp_t    = (const float*)d_in[7];
  const float* inv      = (const float*)d_in[8];
  const float* adj_vals = (const float*)d_in[9];
  const float* r_vals   = (const float*)d_in[10];
  const int*   adj_rows = (const int*)d_in[11];
  const int*   adj_cols = (const int*)d_in[12];
  const int*   r_rows   = (const int*)d_in[13];
  const int*   r_cols   = (const int*)d_in[14];
  float* out = (float*)d_out;
  int Fv = in_sizes[2] / NITEMS;
  int Ft = in_sizes[3] / NITEMS;

  float *p_ihl, *p_uhl, *p_ih, *p_uh, *p_e0, *p_m1, *p_lat;
  float4* p_itfc;
  float4* p_m0c;
  uint32_t *p_e1h, *p_egoh;
  int *p_hist, *pA_cur, *pA_csum, *pA_coff, *pR_cur, *pR_csum, *pR_coff;
  int2 *pA_scv, *pR_scv;
  cudaGetSymbolAddress((void**)&p_itfc, g_itfc);
  cudaGetSymbolAddress((void**)&p_ihl, g_ihl);
  cudaGetSymbolAddress((void**)&p_uhl, g_uhl);
  cudaGetSymbolAddress((void**)&p_ih,  g_ih);
  cudaGetSymbolAddress((void**)&p_uh,  g_uh);
  cudaGetSymbolAddress((void**)&p_e0,  g_e0);
  cudaGetSymbolAddress((void**)&p_egoh, g_egoh);
  cudaGetSymbolAddress((void**)&p_e1h, g_e1h);
  cudaGetSymbolAddress((void**)&p_m0c, g_m0c);
  cudaGetSymbolAddress((void**)&p_m1,  g_m1);
  cudaGetSymbolAddress((void**)&p_lat, g_lat);
  cudaGetSymbolAddress((void**)&p_hist, g_hist);
  cudaGetSymbolAddress((void**)&pA_cur,  g_curA);
  cudaGetSymbolAddress((void**)&pA_scv,  g_scvA);
  cudaGetSymbolAddress((void**)&pA_csum, g_csumA);
  cudaGetSymbolAddress((void**)&pA_coff, g_coffA);
  cudaGetSymbolAddress((void**)&pR_cur,  g_curR);
  cudaGetSymbolAddress((void**)&pR_scv,  g_scvR);
  cudaGetSymbolAddress((void**)&pR_csum, g_csumR);
  cudaGetSymbolAddress((void**)&pR_coff, g_coffR);
  int* pA_start = p_hist;
  int* pR_start = p_hist + NNODES + 1;
  float* p_ihlT = p_ihl + NITEMS * HH;
  float* p_uhlT = p_uhl + NUSERS * HH;
  float* p_ihT  = p_ih + NITEMS * HH;
  float* p_uhT  = p_uh + NUSERS * HH;
  float* p_m1T  = p_m1 + NNODES * EK;
  float* p_latT = p_lat + HH * EK;

  // JAX threefry keys
  uint32_t ki0[2], ki1[2], ku0[2], ku1[2];
  for (int m = 0; m < 2; m++) {
    uint32_t km0, km1;
    tf2x32(0u, 42u, 0u, (uint32_t)m, &km0, &km1);
    tf2x32(km0, km1, 0u, 0u, &ki0[m], &ki1[m]);
    tf2x32(km0, km1, 0u, 1u, &ku0[m], &ku1[m]);
  }

  // ---- zero CSR histograms (one memset) + lat ----
  cudaMemsetAsync(p_hist, 0, HIST_TOTAL * sizeof(int), 0);
  cudaMemsetAsync(p_lat, 0, 2 * HH * EK * sizeof(float), 0);

  // ---- GEMMs + CSR histograms + ego convert in one launch ----
  gemm_hist_kernel<<<dim3(GEMMB + GADJE, 2), 256>>>(
      feat_v, feat_t, trs_v, trs_t, hyp_v, hyp_t,
      (float2*)p_itfc, p_ihl, p_ihlT, Fv, Ft,
      adj_rows, r_rows, pA_start, pR_start,
      Gu, Gi, p_egoh);

  // ---- CSR scans (3 parallel launches) + packed scatter ----
  csr_chunksum2<<<NCHA + NCHR, 256>>>(pA_start, pR_start, pA_csum, pR_csum, NNODES, NUSERS);
  csr_scanchunks2<<<2, 32>>>(pA_csum, pA_coff, pA_start, pR_csum, pR_coff, pR_start);
  csr_chunkscan2<<<NCHA + NCHR, 256>>>(pA_start, pA_coff, pA_cur,
                                       pR_start, pR_coff, pR_cur, NNODES, NUSERS);
  csr_scatter2<<<GADJE + GRE, 256>>>(adj_rows, adj_cols, adj_vals, pA_cur, pA_scv,
                                     r_rows, r_cols, r_vals, pR_cur, pR_scv);

  // ---- phase 2: r_fused(both, inv pre-scaled) + gumbel-items + cge1(bf16 ego gather) ----
  phase2_kernel<<<GUSERB + 2 * GITMB + GNODEB, 256>>>(
      pR_start, pR_scv, p_ihl, p_ihlT, p_itfc, inv,
      p_uhl, p_uhlT, p_m0c,
      p_ih, p_ihT, ki0[0], ki1[0], ki0[1], ki1[1],
      pA_start, pA_scv, p_egoh, p_e1h);

  // ---- phase 3: mega adj (cge2 + mge both, no inv) + gumbel-u ----
  phase3_kernel<<<GNODEB + 2 * GUSERB, 256>>>(
      pA_start, pA_scv, p_e1h,
      (const float2*)Gu, (const float2*)Gi, (float2*)p_e0,
      p_m0c, p_itfc,
      (float2*)p_m1, (float2*)p_m1T,
      p_uhl, p_uhlT, p_uh, p_uhT, ku0[0], ku1[0], ku0[1], ku1[1]);

  // ---- hyper path + final ----
  lat_both_kernel<<<dim3(120, 2), 256>>>(p_ih, p_ihT, p_e0 + NUSERS * EK, p_lat, p_latT, 250);
  final_fused<<<GNODEB, 256>>>(out, p_e0, p_m1, p_m1T,
                               p_ih, p_ihT, p_uh, p_uhT, p_lat, p_latT);
}